// round 3
// baseline (speedup 1.0000x reference)
#include <cuda_runtime.h>
#include <cstdint>

#define C 128
#define NMAX 50176
#define EMAX 800000

// ---------------- device scratch (no allocations allowed) ----------------
__device__ float g_h[NMAX * C];
__device__ float g_P1[NMAX * C];
__device__ float g_QK[NMAX * C];
__device__ float g_KK[NMAX * C];
__device__ float g_v[NMAX * C];
__device__ float g_z[NMAX * C];
__device__ float g_num[NMAX * C];
__device__ float g_Wq[C * C];
__device__ float g_Wk[C * C];
__device__ int g_src[EMAX];
__device__ int g_dst[EMAX];
__device__ int g_is64;

// ---------------- dtype detection: int64 vs packed int32 edge_index ----------------
__global__ void detect_kernel(const void* __restrict__ ei, long long E, int n) {
    const long long* p = (const long long*)ei;
    int ok64 = 1;
    int lim = (E < 64) ? (int)E : 64;
    for (int i = 0; i < lim; i++) {
        long long v = p[i];
        if (v < 0 || v >= n) { ok64 = 0; break; }
    }
    g_is64 = ok64;
}

__global__ void convert_kernel(const void* __restrict__ ei, long long E) {
    long long i = (long long)blockIdx.x * blockDim.x + threadIdx.x;
    if (i >= E) return;
    if (g_is64) {
        const long long* p = (const long long*)ei;
        g_src[i] = (int)p[i];
        g_dst[i] = (int)p[E + i];
    } else {
        const int* p = (const int*)ei;
        g_src[i] = p[i];
        g_dst[i] = p[E + i];
    }
}

// ---------------- zero z / num ----------------
__global__ void zero_kernel(int n) {
    int total = n * C;
    for (int i = (blockIdx.x * blockDim.x + threadIdx.x) * 4; i < total;
         i += gridDim.x * blockDim.x * 4) {
        *(float4*)&g_z[i] = make_float4(0.f, 0.f, 0.f, 0.f);
        *(float4*)&g_num[i] = make_float4(0.f, 0.f, 0.f, 0.f);
    }
}

// ---------------- Wq = W_dst@att_w1, Wk = W_src@att_w1 ----------------
__global__ void precombine_kernel(const float* __restrict__ Wdst,
                                  const float* __restrict__ Wsrc,
                                  const float* __restrict__ att_w1) {
    int r = blockIdx.x;
    int c = threadIdx.x;
    float aq = 0.f, ak = 0.f;
    for (int j = 0; j < C; j++) {
        float w1 = att_w1[j * C + c];
        aq += Wdst[r * C + j] * w1;
        ak += Wsrc[r * C + j] * w1;
    }
    g_Wq[r * C + c] = aq;
    g_Wk[r * C + c] = ak;
}

// ---------------- node kernel 1: h = relu(x@W_in+b_in); P1 = pos@pos_w1 ----------------
__global__ void __launch_bounds__(128, 1)
node1_kernel(const float* __restrict__ x, const float* __restrict__ pos,
             const float* __restrict__ W_in, const float* __restrict__ b_in,
             const float* __restrict__ pos_w1, int n) {
    extern __shared__ float sm[];
    float* sWin = sm;                 // 16384
    float* sWp1 = sm + C * C;         // 16384
    float* sx = sm + 2 * C * C;       // 16*128
    float* sp = sm + 2 * C * C + 16 * C;
    float* sb = sm + 2 * C * C + 32 * C;  // 128

    int tid = threadIdx.x;
    for (int i = tid; i < C * C; i += 128) {
        sWin[i] = W_in[i];
        sWp1[i] = pos_w1[i];
    }
    if (tid < C) sb[tid] = b_in[tid];
    __syncthreads();

    int cg = tid & 31, ng = tid >> 5;
    int nbase = blockIdx.x * 16 + ng * 4;
#pragma unroll
    for (int i = 0; i < 4; i++) {
        int nn = nbase + i;
        if (nn < n) {
            ((float4*)&sx[(ng * 4 + i) * C])[cg] = ((const float4*)&x[(size_t)nn * C])[cg];
            ((float4*)&sp[(ng * 4 + i) * C])[cg] = ((const float4*)&pos[(size_t)nn * C])[cg];
        }
    }
    __syncwarp();

    float4 ah[4], ap[4];
#pragma unroll
    for (int i = 0; i < 4; i++) {
        ah[i] = make_float4(0.f, 0.f, 0.f, 0.f);
        ap[i] = make_float4(0.f, 0.f, 0.f, 0.f);
    }
#pragma unroll 2
    for (int k = 0; k < C; k++) {
        float4 wi = ((float4*)sWin)[k * 32 + cg];
        float4 wp = ((float4*)sWp1)[k * 32 + cg];
#pragma unroll
        for (int i = 0; i < 4; i++) {
            float xv = sx[(ng * 4 + i) * C + k];
            float pv = sp[(ng * 4 + i) * C + k];
            ah[i].x += xv * wi.x; ah[i].y += xv * wi.y;
            ah[i].z += xv * wi.z; ah[i].w += xv * wi.w;
            ap[i].x += pv * wp.x; ap[i].y += pv * wp.y;
            ap[i].z += pv * wp.z; ap[i].w += pv * wp.w;
        }
    }
    float4 bv = ((float4*)sb)[cg];
#pragma unroll
    for (int i = 0; i < 4; i++) {
        int nn = nbase + i;
        if (nn < n) {
            float4 hv;
            hv.x = fmaxf(ah[i].x + bv.x, 0.f);
            hv.y = fmaxf(ah[i].y + bv.y, 0.f);
            hv.z = fmaxf(ah[i].z + bv.z, 0.f);
            hv.w = fmaxf(ah[i].w + bv.w, 0.f);
            ((float4*)&g_h[(size_t)nn * C])[cg] = hv;
            ((float4*)&g_P1[(size_t)nn * C])[cg] = ap[i];
        }
    }
}

// ---------------- node kernel 2: v = h@W_lin; QK = h@Wq; KK = h@Wk ----------------
__global__ void __launch_bounds__(128, 1)
node2_kernel(const float* __restrict__ W_lin, int n) {
    extern __shared__ float sm[];
    float* sWl = sm;
    float* sWq = sm + C * C;
    float* sWk = sm + 2 * C * C;
    float* sh = sm + 3 * C * C;  // 16*128

    int tid = threadIdx.x;
    for (int i = tid; i < C * C; i += 128) {
        sWl[i] = W_lin[i];
        sWq[i] = g_Wq[i];
        sWk[i] = g_Wk[i];
    }
    __syncthreads();

    int cg = tid & 31, ng = tid >> 5;
    int nbase = blockIdx.x * 16 + ng * 4;
#pragma unroll
    for (int i = 0; i < 4; i++) {
        int nn = nbase + i;
        if (nn < n)
            ((float4*)&sh[(ng * 4 + i) * C])[cg] = ((const float4*)&g_h[(size_t)nn * C])[cg];
    }
    __syncwarp();

    float4 av[4], aq[4], ak[4];
#pragma unroll
    for (int i = 0; i < 4; i++) {
        av[i] = make_float4(0.f, 0.f, 0.f, 0.f);
        aq[i] = make_float4(0.f, 0.f, 0.f, 0.f);
        ak[i] = make_float4(0.f, 0.f, 0.f, 0.f);
    }
#pragma unroll 2
    for (int k = 0; k < C; k++) {
        float4 wl = ((float4*)sWl)[k * 32 + cg];
        float4 wq = ((float4*)sWq)[k * 32 + cg];
        float4 wk = ((float4*)sWk)[k * 32 + cg];
#pragma unroll
        for (int i = 0; i < 4; i++) {
            float hv = sh[(ng * 4 + i) * C + k];
            av[i].x += hv * wl.x; av[i].y += hv * wl.y; av[i].z += hv * wl.z; av[i].w += hv * wl.w;
            aq[i].x += hv * wq.x; aq[i].y += hv * wq.y; aq[i].z += hv * wq.z; aq[i].w += hv * wq.w;
            ak[i].x += hv * wk.x; ak[i].y += hv * wk.y; ak[i].z += hv * wk.z; ak[i].w += hv * wk.w;
        }
    }
#pragma unroll
    for (int i = 0; i < 4; i++) {
        int nn = nbase + i;
        if (nn < n) {
            ((float4*)&g_v[(size_t)nn * C])[cg] = av[i];
            ((float4*)&g_QK[(size_t)nn * C])[cg] = aq[i];
            ((float4*)&g_KK[(size_t)nn * C])[cg] = ak[i];
        }
    }
}

// ---------------- edge kernel: single pass ----------------
// per warp: 4 edges, all stages; accumulates z and numerator via float4 atomics
__global__ void __launch_bounds__(256, 1)
edge_kernel(long long E,
            const float* __restrict__ pos_w2, const float* __restrict__ att_w1,
            const float* __restrict__ att_w2, const float* __restrict__ pos_b1,
            const float* __restrict__ pos_b2, const float* __restrict__ att_b1,
            const float* __restrict__ att_b2, int tiles_per_block) {
    extern __shared__ float sm[];
    float* w2 = sm;            // 16384 floats
    float* a1 = sm + 16384;    // 16384
    float* a2 = sm + 32768;    // 16384
    float* tA = sm + 49152;    // 32*128
    float* tB = sm + 53248;    // 32*128
    float* sb = sm + 57344;    // 4*128

    int tid = threadIdx.x;
    for (int i = tid; i < C * C; i += 256) {
        w2[i] = pos_w2[i];
        a1[i] = att_w1[i];
        a2[i] = att_w2[i];
    }
    if (tid < C) {
        sb[tid] = pos_b1[tid];
        sb[C + tid] = pos_b2[tid];
        sb[2 * C + tid] = att_b1[tid];
        sb[3 * C + tid] = att_b2[tid];
    }
    __syncthreads();

    int cg = tid & 31, eg = tid >> 5;
    int c0 = cg * 4;
    int e0 = eg * 4;
    float* tAe = &tA[e0 * C];
    float* tBe = &tB[e0 * C];
    float4 bp1 = ((float4*)sb)[cg];
    float4 bp2 = ((float4*)(sb + C))[cg];
    float4 ba1 = ((float4*)(sb + 2 * C))[cg];
    float4 ba2 = ((float4*)(sb + 3 * C))[cg];

    long long tile0 = (long long)blockIdx.x * tiles_per_block;
    for (int t = 0; t < tiles_per_block; t++) {
        long long ebase = (tile0 + t) * 32;
        if (ebase >= E) break;

        int src[4], dst[4];
        bool val[4];
#pragma unroll
        for (int i = 0; i < 4; i++) {
            long long eG = ebase + e0 + i;
            val[i] = (eG < E);
            src[i] = val[i] ? g_src[eG] : 0;
            dst[i] = val[i] ? g_dst[eG] : 0;
        }

        // stage 0: t1 = relu(P1[dst]-P1[src]+pos_b1)
#pragma unroll
        for (int i = 0; i < 4; i++) {
            float4 pd = ((const float4*)&g_P1[(size_t)dst[i] * C])[cg];
            float4 ps = ((const float4*)&g_P1[(size_t)src[i] * C])[cg];
            float4 tv;
            tv.x = fmaxf(pd.x - ps.x + bp1.x, 0.f);
            tv.y = fmaxf(pd.y - ps.y + bp1.y, 0.f);
            tv.z = fmaxf(pd.z - ps.z + bp1.z, 0.f);
            tv.w = fmaxf(pd.w - ps.w + bp1.w, 0.f);
            ((float4*)&tAe[i * C])[cg] = tv;
        }
        __syncwarp();

        // stage 1: delta = relu(t1 @ pos_w2 + pos_b2)
        float4 acc[4];
#pragma unroll
        for (int i = 0; i < 4; i++) acc[i] = make_float4(0.f, 0.f, 0.f, 0.f);
#pragma unroll 2
        for (int k = 0; k < C; k++) {
            float4 w = ((float4*)w2)[k * 32 + cg];
#pragma unroll
            for (int i = 0; i < 4; i++) {
                float tv = tAe[i * C + k];
                acc[i].x += tv * w.x; acc[i].y += tv * w.y;
                acc[i].z += tv * w.z; acc[i].w += tv * w.w;
            }
        }
        float4 dl[4];
#pragma unroll
        for (int i = 0; i < 4; i++) {
            dl[i].x = fmaxf(acc[i].x + bp2.x, 0.f);
            dl[i].y = fmaxf(acc[i].y + bp2.y, 0.f);
            dl[i].z = fmaxf(acc[i].z + bp2.z, 0.f);
            dl[i].w = fmaxf(acc[i].w + bp2.w, 0.f);
            ((float4*)&tBe[i * C])[cg] = dl[i];
        }
        __syncwarp();

        // stage 2: t2 = relu(QK[dst]-KK[src] + delta@att_w1 + att_b1)
#pragma unroll
        for (int i = 0; i < 4; i++) acc[i] = make_float4(0.f, 0.f, 0.f, 0.f);
#pragma unroll 2
        for (int k = 0; k < C; k++) {
            float4 w = ((float4*)a1)[k * 32 + cg];
#pragma unroll
            for (int i = 0; i < 4; i++) {
                float tv = tBe[i * C + k];
                acc[i].x += tv * w.x; acc[i].y += tv * w.y;
                acc[i].z += tv * w.z; acc[i].w += tv * w.w;
            }
        }
#pragma unroll
        for (int i = 0; i < 4; i++) {
            float4 qk = ((const float4*)&g_QK[(size_t)dst[i] * C])[cg];
            float4 kk = ((const float4*)&g_KK[(size_t)src[i] * C])[cg];
            float4 tv;
            tv.x = fmaxf(qk.x - kk.x + acc[i].x + ba1.x, 0.f);
            tv.y = fmaxf(qk.y - kk.y + acc[i].y + ba1.y, 0.f);
            tv.z = fmaxf(qk.z - kk.z + acc[i].z + ba1.z, 0.f);
            tv.w = fmaxf(qk.w - kk.w + acc[i].w + ba1.w, 0.f);
            ((float4*)&tAe[i * C])[cg] = tv;
        }
        __syncwarp();

        // stage 3: alpha = relu(t2 @ att_w2 + att_b2); accumulate softmax pieces
#pragma unroll
        for (int i = 0; i < 4; i++) acc[i] = make_float4(0.f, 0.f, 0.f, 0.f);
#pragma unroll 2
        for (int k = 0; k < C; k++) {
            float4 w = ((float4*)a2)[k * 32 + cg];
#pragma unroll
            for (int i = 0; i < 4; i++) {
                float tv = tAe[i * C + k];
                acc[i].x += tv * w.x; acc[i].y += tv * w.y;
                acc[i].z += tv * w.z; acc[i].w += tv * w.w;
            }
        }
#pragma unroll
        for (int i = 0; i < 4; i++) {
            if (!val[i]) continue;
            float4 ez;
            ez.x = __expf(fmaxf(acc[i].x + ba2.x, 0.f));
            ez.y = __expf(fmaxf(acc[i].y + ba2.y, 0.f));
            ez.z = __expf(fmaxf(acc[i].z + ba2.z, 0.f));
            ez.w = __expf(fmaxf(acc[i].w + ba2.w, 0.f));
            float4 vv = ((const float4*)&g_v[(size_t)src[i] * C])[cg];
            float4 nm;
            nm.x = ez.x * (vv.x + dl[i].x);
            nm.y = ez.y * (vv.y + dl[i].y);
            nm.z = ez.z * (vv.z + dl[i].z);
            nm.w = ez.w * (vv.w + dl[i].w);
            atomicAdd((float4*)&g_z[(size_t)dst[i] * C + c0], ez);
            atomicAdd((float4*)&g_num[(size_t)dst[i] * C + c0], nm);
        }
        __syncwarp();
    }
}

// ---------------- out kernel: out = relu((num/(z+eps)) @ W_out + b_out) ----------------
__global__ void __launch_bounds__(128, 1)
out_kernel(const float* __restrict__ W_out, const float* __restrict__ b_out,
           float* __restrict__ out, int n) {
    extern __shared__ float sm[];
    float* sW = sm;            // 16384
    float* srow = sm + C * C;  // 16*128
    float* sb = sm + C * C + 16 * C;

    int tid = threadIdx.x;
    for (int i = tid; i < C * C; i += 128) sW[i] = W_out[i];
    if (tid < C) sb[tid] = b_out[tid];
    __syncthreads();

    int cg = tid & 31, ng = tid >> 5;
    int nbase = blockIdx.x * 16 + ng * 4;
#pragma unroll
    for (int i = 0; i < 4; i++) {
        int nn = nbase + i;
        if (nn < n) {
            float4 nm = ((const float4*)&g_num[(size_t)nn * C])[cg];
            float4 zz = ((const float4*)&g_z[(size_t)nn * C])[cg];
            float4 ag;
            ag.x = nm.x / (zz.x + 1e-16f);
            ag.y = nm.y / (zz.y + 1e-16f);
            ag.z = nm.z / (zz.z + 1e-16f);
            ag.w = nm.w / (zz.w + 1e-16f);
            ((float4*)&srow[(ng * 4 + i) * C])[cg] = ag;
        }
    }
    __syncwarp();

    float4 acc[4];
#pragma unroll
    for (int i = 0; i < 4; i++) acc[i] = make_float4(0.f, 0.f, 0.f, 0.f);
#pragma unroll 2
    for (int k = 0; k < C; k++) {
        float4 w = ((float4*)sW)[k * 32 + cg];
#pragma unroll
        for (int i = 0; i < 4; i++) {
            float av = srow[(ng * 4 + i) * C + k];
            acc[i].x += av * w.x; acc[i].y += av * w.y;
            acc[i].z += av * w.z; acc[i].w += av * w.w;
        }
    }
    float4 bv = ((float4*)sb)[cg];
#pragma unroll
    for (int i = 0; i < 4; i++) {
        int nn = nbase + i;
        if (nn < n) {
            float4 ov;
            ov.x = fmaxf(acc[i].x + bv.x, 0.f);
            ov.y = fmaxf(acc[i].y + bv.y, 0.f);
            ov.z = fmaxf(acc[i].z + bv.z, 0.f);
            ov.w = fmaxf(acc[i].w + bv.w, 0.f);
            ((float4*)&out[(size_t)nn * C])[cg] = ov;
        }
    }
}

// ---------------- launch ----------------
extern "C" void kernel_launch(void* const* d_in, const int* in_sizes, int n_in,
                              void* d_out, int out_size) {
    const float* x = (const float*)d_in[0];
    const float* pos = (const float*)d_in[1];
    const void* ei = d_in[2];
    const float* W_in = (const float*)d_in[3];
    const float* b_in = (const float*)d_in[4];
    const float* W_lin = (const float*)d_in[5];
    const float* W_src = (const float*)d_in[6];
    const float* W_dst = (const float*)d_in[7];
    const float* pos_w1 = (const float*)d_in[8];
    const float* pos_b1 = (const float*)d_in[9];
    const float* pos_w2 = (const float*)d_in[10];
    const float* pos_b2 = (const float*)d_in[11];
    const float* att_w1 = (const float*)d_in[12];
    const float* att_b1 = (const float*)d_in[13];
    const float* att_w2 = (const float*)d_in[14];
    const float* att_b2 = (const float*)d_in[15];
    const float* W_out = (const float*)d_in[16];
    const float* b_out = (const float*)d_in[17];

    int n = in_sizes[0] / C;
    long long E = in_sizes[2] / 2;

    const int SZ1 = (2 * C * C + 32 * C + C) * 4;            // 147968
    const int SZ2 = (3 * C * C + 16 * C) * 4;                // 204800
    const int SZE = (3 * C * C + 64 * C + 4 * C) * 4;        // 231424
    const int SZO = (C * C + 16 * C + C) * 4;                // 74240

    cudaFuncSetAttribute(node1_kernel, cudaFuncAttributeMaxDynamicSharedMemorySize, SZ1);
    cudaFuncSetAttribute(node2_kernel, cudaFuncAttributeMaxDynamicSharedMemorySize, SZ2);
    cudaFuncSetAttribute(edge_kernel, cudaFuncAttributeMaxDynamicSharedMemorySize, SZE);
    cudaFuncSetAttribute(out_kernel, cudaFuncAttributeMaxDynamicSharedMemorySize, SZO);

    detect_kernel<<<1, 1>>>(ei, E, n);
    convert_kernel<<<(int)((E + 255) / 256), 256>>>(ei, E);

    zero_kernel<<<512, 256>>>(n);
    precombine_kernel<<<C, C>>>(W_dst, W_src, att_w1);

    int nb = (n + 15) / 16;
    node1_kernel<<<nb, 128, SZ1>>>(x, pos, W_in, b_in, pos_w1, n);
    node2_kernel<<<nb, 128, SZ2>>>(W_lin, n);

    long long tiles = (E + 31) / 32;
    int tpb = 8;
    int eb = (int)((tiles + tpb - 1) / tpb);
    edge_kernel<<<eb, 256, SZE>>>(E, pos_w2, att_w1, att_w2,
                                  pos_b1, pos_b2, att_b1, att_b2, tpb);

    out_kernel<<<nb, 128, SZO>>>(W_out, b_out, (float*)d_out, n);
}

// round 4
// speedup vs baseline: 1.1663x; 1.1663x over previous
#include <cuda_runtime.h>
#include <cstdint>

#define C 128
#define NMAX 50176
#define EMAX 800000

// ---------------- device scratch ----------------
__device__ float g_h[NMAX * C];
__device__ float g_P1[NMAX * C];
__device__ float g_QK[NMAX * C];
__device__ float g_KK[NMAX * C];
__device__ float g_v[NMAX * C];
__device__ float g_z[NMAX * C];
__device__ float g_num[NMAX * C];
__device__ float g_Wq[C * C];
__device__ float g_Wk[C * C];
__device__ int g_src[EMAX];
__device__ int g_dst[EMAX];
__device__ int g_is64;

// ---------------- f32x2 helpers ----------------
__device__ __forceinline__ unsigned long long fma2(unsigned long long a,
                                                   unsigned long long b,
                                                   unsigned long long c) {
    unsigned long long d;
    asm("fma.rn.f32x2 %0, %1, %2, %3;" : "=l"(d) : "l"(a), "l"(b), "l"(c));
    return d;
}
__device__ __forceinline__ unsigned long long dup2(float v) {
    unsigned long long r;
    unsigned int u = __float_as_uint(v);
    asm("mov.b64 %0, {%1, %1};" : "=l"(r) : "r"(u));
    return r;
}
__device__ __forceinline__ float2 unpack2(unsigned long long p) {
    unsigned int lo, hi;
    asm("mov.b64 {%0, %1}, %2;" : "=r"(lo), "=r"(hi) : "l"(p));
    return make_float2(__uint_as_float(lo), __uint_as_float(hi));
}

// ---------------- dtype detection: int64 vs packed int32 edge_index ----------------
__global__ void detect_kernel(const void* __restrict__ ei, long long E, int n) {
    const long long* p = (const long long*)ei;
    int ok64 = 1;
    int lim = (E < 64) ? (int)E : 64;
    for (int i = 0; i < lim; i++) {
        long long v = p[i];
        if (v < 0 || v >= n) { ok64 = 0; break; }
    }
    g_is64 = ok64;
}

__global__ void convert_kernel(const void* __restrict__ ei, long long E) {
    long long i = (long long)blockIdx.x * blockDim.x + threadIdx.x;
    if (i >= E) return;
    if (g_is64) {
        const long long* p = (const long long*)ei;
        g_src[i] = (int)p[i];
        g_dst[i] = (int)p[E + i];
    } else {
        const int* p = (const int*)ei;
        g_src[i] = p[i];
        g_dst[i] = p[E + i];
    }
}

// ---------------- zero z / num ----------------
__global__ void zero_kernel(int n) {
    int total = n * C;
    for (int i = (blockIdx.x * blockDim.x + threadIdx.x) * 4; i < total;
         i += gridDim.x * blockDim.x * 4) {
        *(float4*)&g_z[i] = make_float4(0.f, 0.f, 0.f, 0.f);
        *(float4*)&g_num[i] = make_float4(0.f, 0.f, 0.f, 0.f);
    }
}

// ---------------- Wq = W_dst@att_w1, Wk = W_src@att_w1 ----------------
__global__ void precombine_kernel(const float* __restrict__ Wdst,
                                  const float* __restrict__ Wsrc,
                                  const float* __restrict__ att_w1) {
    int r = blockIdx.x;
    int c = threadIdx.x;
    float aq = 0.f, ak = 0.f;
    for (int j = 0; j < C; j++) {
        float w1 = att_w1[j * C + c];
        aq += Wdst[r * C + j] * w1;
        ak += Wsrc[r * C + j] * w1;
    }
    g_Wq[r * C + c] = aq;
    g_Wk[r * C + c] = ak;
}

// ---------------- node kernel 1: h = relu(x@W_in+b_in); P1 = pos@pos_w1 ----------------
__global__ void __launch_bounds__(128, 1)
node1_kernel(const float* __restrict__ x, const float* __restrict__ pos,
             const float* __restrict__ W_in, const float* __restrict__ b_in,
             const float* __restrict__ pos_w1, int n) {
    extern __shared__ float sm[];
    float* sWin = sm;
    float* sWp1 = sm + C * C;
    float* sx = sm + 2 * C * C;
    float* sp = sm + 2 * C * C + 16 * C;
    float* sb = sm + 2 * C * C + 32 * C;

    int tid = threadIdx.x;
    for (int i = tid; i < C * C; i += 128) {
        sWin[i] = W_in[i];
        sWp1[i] = pos_w1[i];
    }
    if (tid < C) sb[tid] = b_in[tid];
    __syncthreads();

    int cg = tid & 31, ng = tid >> 5;
    int nbase = blockIdx.x * 16 + ng * 4;
#pragma unroll
    for (int i = 0; i < 4; i++) {
        int nn = nbase + i;
        if (nn < n) {
            ((float4*)&sx[(ng * 4 + i) * C])[cg] = ((const float4*)&x[(size_t)nn * C])[cg];
            ((float4*)&sp[(ng * 4 + i) * C])[cg] = ((const float4*)&pos[(size_t)nn * C])[cg];
        }
    }
    __syncwarp();

    float4 ah[4], ap[4];
#pragma unroll
    for (int i = 0; i < 4; i++) {
        ah[i] = make_float4(0.f, 0.f, 0.f, 0.f);
        ap[i] = make_float4(0.f, 0.f, 0.f, 0.f);
    }
#pragma unroll 2
    for (int k = 0; k < C; k++) {
        float4 wi = ((float4*)sWin)[k * 32 + cg];
        float4 wp = ((float4*)sWp1)[k * 32 + cg];
#pragma unroll
        for (int i = 0; i < 4; i++) {
            float xv = sx[(ng * 4 + i) * C + k];
            float pv = sp[(ng * 4 + i) * C + k];
            ah[i].x += xv * wi.x; ah[i].y += xv * wi.y;
            ah[i].z += xv * wi.z; ah[i].w += xv * wi.w;
            ap[i].x += pv * wp.x; ap[i].y += pv * wp.y;
            ap[i].z += pv * wp.z; ap[i].w += pv * wp.w;
        }
    }
    float4 bv = ((float4*)sb)[cg];
#pragma unroll
    for (int i = 0; i < 4; i++) {
        int nn = nbase + i;
        if (nn < n) {
            float4 hv;
            hv.x = fmaxf(ah[i].x + bv.x, 0.f);
            hv.y = fmaxf(ah[i].y + bv.y, 0.f);
            hv.z = fmaxf(ah[i].z + bv.z, 0.f);
            hv.w = fmaxf(ah[i].w + bv.w, 0.f);
            ((float4*)&g_h[(size_t)nn * C])[cg] = hv;
            ((float4*)&g_P1[(size_t)nn * C])[cg] = ap[i];
        }
    }
}

// ---------------- node kernel 2: v = h@W_lin; QK = h@Wq; KK = h@Wk ----------------
__global__ void __launch_bounds__(128, 1)
node2_kernel(const float* __restrict__ W_lin, int n) {
    extern __shared__ float sm[];
    float* sWl = sm;
    float* sWq = sm + C * C;
    float* sWk = sm + 2 * C * C;
    float* sh = sm + 3 * C * C;

    int tid = threadIdx.x;
    for (int i = tid; i < C * C; i += 128) {
        sWl[i] = W_lin[i];
        sWq[i] = g_Wq[i];
        sWk[i] = g_Wk[i];
    }
    __syncthreads();

    int cg = tid & 31, ng = tid >> 5;
    int nbase = blockIdx.x * 16 + ng * 4;
#pragma unroll
    for (int i = 0; i < 4; i++) {
        int nn = nbase + i;
        if (nn < n)
            ((float4*)&sh[(ng * 4 + i) * C])[cg] = ((const float4*)&g_h[(size_t)nn * C])[cg];
    }
    __syncwarp();

    float4 av[4], aq[4], ak[4];
#pragma unroll
    for (int i = 0; i < 4; i++) {
        av[i] = make_float4(0.f, 0.f, 0.f, 0.f);
        aq[i] = make_float4(0.f, 0.f, 0.f, 0.f);
        ak[i] = make_float4(0.f, 0.f, 0.f, 0.f);
    }
#pragma unroll 2
    for (int k = 0; k < C; k++) {
        float4 wl = ((float4*)sWl)[k * 32 + cg];
        float4 wq = ((float4*)sWq)[k * 32 + cg];
        float4 wk = ((float4*)sWk)[k * 32 + cg];
#pragma unroll
        for (int i = 0; i < 4; i++) {
            float hv = sh[(ng * 4 + i) * C + k];
            av[i].x += hv * wl.x; av[i].y += hv * wl.y; av[i].z += hv * wl.z; av[i].w += hv * wl.w;
            aq[i].x += hv * wq.x; aq[i].y += hv * wq.y; aq[i].z += hv * wq.z; aq[i].w += hv * wq.w;
            ak[i].x += hv * wk.x; ak[i].y += hv * wk.y; ak[i].z += hv * wk.z; ak[i].w += hv * wk.w;
        }
    }
#pragma unroll
    for (int i = 0; i < 4; i++) {
        int nn = nbase + i;
        if (nn < n) {
            ((float4*)&g_v[(size_t)nn * C])[cg] = av[i];
            ((float4*)&g_QK[(size_t)nn * C])[cg] = aq[i];
            ((float4*)&g_KK[(size_t)nn * C])[cg] = ak[i];
        }
    }
}

// ---------------- edge kernel: single pass, f32x2, 8 edges/warp ----------------
// 256 threads = 8 warps x 8 edges = 64 edges/tile.
// smem: 3 weight mats (196608B) + tA (64x128 = 32768B) + biases (2048B) = 231424B
__global__ void __launch_bounds__(256, 1)
edge_kernel(long long E,
            const float* __restrict__ pos_w2, const float* __restrict__ att_w1,
            const float* __restrict__ att_w2, const float* __restrict__ pos_b1,
            const float* __restrict__ pos_b2, const float* __restrict__ att_b1,
            const float* __restrict__ att_b2, int tiles_per_block) {
    extern __shared__ float sm[];
    float* w2 = sm;            // 16384 floats
    float* a1 = sm + 16384;
    float* a2 = sm + 32768;
    float* tA = sm + 49152;    // 64*128 floats
    float* sb = sm + 57344;    // 4*128

    int tid = threadIdx.x;
    for (int i = tid; i < C * C; i += 256) {
        w2[i] = pos_w2[i];
        a1[i] = att_w1[i];
        a2[i] = att_w2[i];
    }
    if (tid < C) {
        sb[tid] = pos_b1[tid];
        sb[C + tid] = pos_b2[tid];
        sb[2 * C + tid] = att_b1[tid];
        sb[3 * C + tid] = att_b2[tid];
    }
    __syncthreads();

    int cg = tid & 31, eg = tid >> 5;
    int c0 = cg * 4;
    float* tAe = &tA[eg * 8 * C];
    float4 bp1 = ((float4*)sb)[cg];
    float4 bp2 = ((float4*)(sb + C))[cg];
    float4 ba1 = ((float4*)(sb + 2 * C))[cg];
    float4 ba2 = ((float4*)(sb + 3 * C))[cg];

    long long tile0 = (long long)blockIdx.x * tiles_per_block;
    for (int t = 0; t < tiles_per_block; t++) {
        long long ebase = (tile0 + t) * 64;
        if (ebase >= E) break;

        int src[8], dst[8];
        bool val[8];
#pragma unroll
        for (int i = 0; i < 8; i++) {
            long long eG = ebase + eg * 8 + i;
            val[i] = (eG < E);
            src[i] = val[i] ? g_src[eG] : 0;
            dst[i] = val[i] ? g_dst[eG] : 0;
        }

        // stage 0: tA = relu(P1[dst]-P1[src]+pos_b1)
#pragma unroll
        for (int i = 0; i < 8; i++) {
            float4 pd = ((const float4*)&g_P1[(size_t)dst[i] * C])[cg];
            float4 ps = ((const float4*)&g_P1[(size_t)src[i] * C])[cg];
            float4 tv;
            tv.x = fmaxf(pd.x - ps.x + bp1.x, 0.f);
            tv.y = fmaxf(pd.y - ps.y + bp1.y, 0.f);
            tv.z = fmaxf(pd.z - ps.z + bp1.z, 0.f);
            tv.w = fmaxf(pd.w - ps.w + bp1.w, 0.f);
            ((float4*)&tAe[i * C])[cg] = tv;
        }
        __syncwarp();

        unsigned long long acc0[8], acc1[8];

        // stage 1: delta = relu(tA @ pos_w2 + pos_b2)  [f32x2]
#pragma unroll
        for (int i = 0; i < 8; i++) { acc0[i] = 0ull; acc1[i] = 0ull; }
#pragma unroll 2
        for (int k4 = 0; k4 < 32; k4++) {
            float4 tv4[8];
#pragma unroll
            for (int i = 0; i < 8; i++) tv4[i] = ((const float4*)&tAe[i * C])[k4];
#pragma unroll
            for (int c = 0; c < 4; c++) {
                ulonglong2 w = ((const ulonglong2*)w2)[(k4 * 4 + c) * 32 + cg];
#pragma unroll
                for (int i = 0; i < 8; i++) {
                    float tv = (c == 0) ? tv4[i].x : (c == 1) ? tv4[i].y
                             : (c == 2) ? tv4[i].z : tv4[i].w;
                    unsigned long long tt = dup2(tv);
                    acc0[i] = fma2(tt, w.x, acc0[i]);
                    acc1[i] = fma2(tt, w.y, acc1[i]);
                }
            }
        }
        float dlf[8][4];
#pragma unroll
        for (int i = 0; i < 8; i++) {
            float2 lo = unpack2(acc0[i]);
            float2 hi = unpack2(acc1[i]);
            dlf[i][0] = fmaxf(lo.x + bp2.x, 0.f);
            dlf[i][1] = fmaxf(lo.y + bp2.y, 0.f);
            dlf[i][2] = fmaxf(hi.x + bp2.z, 0.f);
            dlf[i][3] = fmaxf(hi.y + bp2.w, 0.f);
        }
        __syncwarp();

        // stage 2: t2 = relu(QK[dst]-KK[src] + delta@att_w1 + att_b1)
        // delta lives in registers; broadcast via shfl (lane k4 holds ch 4*k4+c)
#pragma unroll
        for (int i = 0; i < 8; i++) { acc0[i] = 0ull; acc1[i] = 0ull; }
#pragma unroll 2
        for (int k4 = 0; k4 < 32; k4++) {
#pragma unroll
            for (int c = 0; c < 4; c++) {
                ulonglong2 w = ((const ulonglong2*)a1)[(k4 * 4 + c) * 32 + cg];
#pragma unroll
                for (int i = 0; i < 8; i++) {
                    float tv = __shfl_sync(0xffffffffu, dlf[i][c], k4);
                    unsigned long long tt = dup2(tv);
                    acc0[i] = fma2(tt, w.x, acc0[i]);
                    acc1[i] = fma2(tt, w.y, acc1[i]);
                }
            }
        }
#pragma unroll
        for (int i = 0; i < 8; i++) {
            float4 qk = ((const float4*)&g_QK[(size_t)dst[i] * C])[cg];
            float4 kk = ((const float4*)&g_KK[(size_t)src[i] * C])[cg];
            float2 lo = unpack2(acc0[i]);
            float2 hi = unpack2(acc1[i]);
            float4 tv;
            tv.x = fmaxf(qk.x - kk.x + lo.x + ba1.x, 0.f);
            tv.y = fmaxf(qk.y - kk.y + lo.y + ba1.y, 0.f);
            tv.z = fmaxf(qk.z - kk.z + hi.x + ba1.z, 0.f);
            tv.w = fmaxf(qk.w - kk.w + hi.y + ba1.w, 0.f);
            ((float4*)&tAe[i * C])[cg] = tv;
        }
        __syncwarp();

        // stage 3: alpha = relu(tA @ att_w2 + att_b2); softmax accumulation
#pragma unroll
        for (int i = 0; i < 8; i++) { acc0[i] = 0ull; acc1[i] = 0ull; }
#pragma unroll 2
        for (int k4 = 0; k4 < 32; k4++) {
            float4 tv4[8];
#pragma unroll
            for (int i = 0; i < 8; i++) tv4[i] = ((const float4*)&tAe[i * C])[k4];
#pragma unroll
            for (int c = 0; c < 4; c++) {
                ulonglong2 w = ((const ulonglong2*)a2)[(k4 * 4 + c) * 32 + cg];
#pragma unroll
                for (int i = 0; i < 8; i++) {
                    float tv = (c == 0) ? tv4[i].x : (c == 1) ? tv4[i].y
                             : (c == 2) ? tv4[i].z : tv4[i].w;
                    unsigned long long tt = dup2(tv);
                    acc0[i] = fma2(tt, w.x, acc0[i]);
                    acc1[i] = fma2(tt, w.y, acc1[i]);
                }
            }
        }
#pragma unroll
        for (int i = 0; i < 8; i++) {
            if (!val[i]) continue;
            float2 lo = unpack2(acc0[i]);
            float2 hi = unpack2(acc1[i]);
            float4 ez;
            ez.x = __expf(fmaxf(lo.x + ba2.x, 0.f));
            ez.y = __expf(fmaxf(lo.y + ba2.y, 0.f));
            ez.z = __expf(fmaxf(hi.x + ba2.z, 0.f));
            ez.w = __expf(fmaxf(hi.y + ba2.w, 0.f));
            float4 vv = ((const float4*)&g_v[(size_t)src[i] * C])[cg];
            float4 nm;
            nm.x = ez.x * (vv.x + dlf[i][0]);
            nm.y = ez.y * (vv.y + dlf[i][1]);
            nm.z = ez.z * (vv.z + dlf[i][2]);
            nm.w = ez.w * (vv.w + dlf[i][3]);
            atomicAdd((float4*)&g_z[(size_t)dst[i] * C + c0], ez);
            atomicAdd((float4*)&g_num[(size_t)dst[i] * C + c0], nm);
        }
        __syncwarp();
    }
}

// ---------------- out kernel: out = relu((num/(z+eps)) @ W_out + b_out) ----------------
__global__ void __launch_bounds__(128, 1)
out_kernel(const float* __restrict__ W_out, const float* __restrict__ b_out,
           float* __restrict__ out, int n) {
    extern __shared__ float sm[];
    float* sW = sm;
    float* srow = sm + C * C;
    float* sb = sm + C * C + 16 * C;

    int tid = threadIdx.x;
    for (int i = tid; i < C * C; i += 128) sW[i] = W_out[i];
    if (tid < C) sb[tid] = b_out[tid];
    __syncthreads();

    int cg = tid & 31, ng = tid >> 5;
    int nbase = blockIdx.x * 16 + ng * 4;
#pragma unroll
    for (int i = 0; i < 4; i++) {
        int nn = nbase + i;
        if (nn < n) {
            float4 nm = ((const float4*)&g_num[(size_t)nn * C])[cg];
            float4 zz = ((const float4*)&g_z[(size_t)nn * C])[cg];
            float4 ag;
            ag.x = nm.x / (zz.x + 1e-16f);
            ag.y = nm.y / (zz.y + 1e-16f);
            ag.z = nm.z / (zz.z + 1e-16f);
            ag.w = nm.w / (zz.w + 1e-16f);
            ((float4*)&srow[(ng * 4 + i) * C])[cg] = ag;
        }
    }
    __syncwarp();

    float4 acc[4];
#pragma unroll
    for (int i = 0; i < 4; i++) acc[i] = make_float4(0.f, 0.f, 0.f, 0.f);
#pragma unroll 2
    for (int k = 0; k < C; k++) {
        float4 w = ((float4*)sW)[k * 32 + cg];
#pragma unroll
        for (int i = 0; i < 4; i++) {
            float av = srow[(ng * 4 + i) * C + k];
            acc[i].x += av * w.x; acc[i].y += av * w.y;
            acc[i].z += av * w.z; acc[i].w += av * w.w;
        }
    }
    float4 bv = ((float4*)sb)[cg];
#pragma unroll
    for (int i = 0; i < 4; i++) {
        int nn = nbase + i;
        if (nn < n) {
            float4 ov;
            ov.x = fmaxf(acc[i].x + bv.x, 0.f);
            ov.y = fmaxf(acc[i].y + bv.y, 0.f);
            ov.z = fmaxf(acc[i].z + bv.z, 0.f);
            ov.w = fmaxf(acc[i].w + bv.w, 0.f);
            ((float4*)&out[(size_t)nn * C])[cg] = ov;
        }
    }
}

// ---------------- launch ----------------
extern "C" void kernel_launch(void* const* d_in, const int* in_sizes, int n_in,
                              void* d_out, int out_size) {
    const float* x = (const float*)d_in[0];
    const float* pos = (const float*)d_in[1];
    const void* ei = d_in[2];
    const float* W_in = (const float*)d_in[3];
    const float* b_in = (const float*)d_in[4];
    const float* W_lin = (const float*)d_in[5];
    const float* W_src = (const float*)d_in[6];
    const float* W_dst = (const float*)d_in[7];
    const float* pos_w1 = (const float*)d_in[8];
    const float* pos_b1 = (const float*)d_in[9];
    const float* pos_w2 = (const float*)d_in[10];
    const float* pos_b2 = (const float*)d_in[11];
    const float* att_w1 = (const float*)d_in[12];
    const float* att_b1 = (const float*)d_in[13];
    const float* att_w2 = (const float*)d_in[14];
    const float* att_b2 = (const float*)d_in[15];
    const float* W_out = (const float*)d_in[16];
    const float* b_out = (const float*)d_in[17];

    int n = in_sizes[0] / C;
    long long E = in_sizes[2] / 2;

    const int SZ1 = (2 * C * C + 32 * C + C) * 4;
    const int SZ2 = (3 * C * C + 16 * C) * 4;
    const int SZE = (3 * C * C + 64 * C + 4 * C) * 4;   // 231424
    const int SZO = (C * C + 16 * C + C) * 4;

    cudaFuncSetAttribute(node1_kernel, cudaFuncAttributeMaxDynamicSharedMemorySize, SZ1);
    cudaFuncSetAttribute(node2_kernel, cudaFuncAttributeMaxDynamicSharedMemorySize, SZ2);
    cudaFuncSetAttribute(edge_kernel, cudaFuncAttributeMaxDynamicSharedMemorySize, SZE);
    cudaFuncSetAttribute(out_kernel, cudaFuncAttributeMaxDynamicSharedMemorySize, SZO);

    detect_kernel<<<1, 1>>>(ei, E, n);
    convert_kernel<<<(int)((E + 255) / 256), 256>>>(ei, E);

    zero_kernel<<<512, 256>>>(n);
    precombine_kernel<<<C, C>>>(W_dst, W_src, att_w1);

    int nb = (n + 15) / 16;
    node1_kernel<<<nb, 128, SZ1>>>(x, pos, W_in, b_in, pos_w1, n);
    node2_kernel<<<nb, 128, SZ2>>>(W_lin, n);

    long long tiles = (E + 63) / 64;
    int tpb = 8;
    int eb = (int)((tiles + tpb - 1) / tpb);
    edge_kernel<<<eb, 256, SZE>>>(E, pos_w2, att_w1, att_w2,
                                  pos_b1, pos_b2, att_b1, att_b2, tpb);

    out_kernel<<<nb, 128, SZO>>>(W_out, b_out, (float*)d_out, n);
}

// round 6
// speedup vs baseline: 1.4616x; 1.2532x over previous
#include <cuda_runtime.h>
#include <cuda_fp16.h>
#include <cstdint>

#define C 128
#define NMAX 50176
#define EMAX 800000

// ---------------- device scratch ----------------
__device__ float g_h[NMAX * C];
__device__ float g_P1[NMAX * C];
__device__ float g_QK[NMAX * C];
__device__ float g_KK[NMAX * C];
__device__ float g_v[NMAX * C];
__device__ float g_z[NMAX * C];
__device__ float g_num[NMAX * C];
__device__ float g_Wq[C * C];
__device__ float g_Wk[C * C];
__device__ int g_src[EMAX];
__device__ int g_dst[EMAX];
__device__ int g_is64;
// fp16 transposed edge-GEMM weights: B[n][k] = W[k][n]
__device__ __half g_B1h[C * C];   // pos_w2^T
__device__ __half g_B2h[C * C];   // att_w1^T
__device__ __half g_B3h[C * C];   // att_w2^T

// ---------------- mma helpers (base-target sm_80+ instructions only) ----------------
__device__ __forceinline__ uint32_t smem_u32(const void* p) {
    uint32_t a;
    asm("{ .reg .u64 t; cvta.to.shared.u64 t, %1; cvt.u32.u64 %0, t; }" : "=r"(a) : "l"(p));
    return a;
}
__device__ __forceinline__ void ldsm_x4(uint32_t addr, uint32_t& r0, uint32_t& r1,
                                        uint32_t& r2, uint32_t& r3) {
    asm volatile("ldmatrix.sync.aligned.m8n8.x4.shared.b16 {%0,%1,%2,%3}, [%4];"
                 : "=r"(r0), "=r"(r1), "=r"(r2), "=r"(r3) : "r"(addr));
}
__device__ __forceinline__ void ldsm_x2(uint32_t addr, uint32_t& r0, uint32_t& r1) {
    asm volatile("ldmatrix.sync.aligned.m8n8.x2.shared.b16 {%0,%1}, [%2];"
                 : "=r"(r0), "=r"(r1) : "r"(addr));
}
__device__ __forceinline__ void mma_16816(float* acc, uint32_t a0, uint32_t a1,
                                          uint32_t a2, uint32_t a3,
                                          uint32_t b0, uint32_t b1) {
    asm volatile(
        "mma.sync.aligned.m16n8k16.row.col.f32.f16.f16.f32 "
        "{%0,%1,%2,%3}, {%4,%5,%6,%7}, {%8,%9}, {%0,%1,%2,%3};"
        : "+f"(acc[0]), "+f"(acc[1]), "+f"(acc[2]), "+f"(acc[3])
        : "r"(a0), "r"(a1), "r"(a2), "r"(a3), "r"(b0), "r"(b1));
}

// smem layout (bytes). Rows padded to 272B (136 halfs) -> conflict-free ldmatrix.
#define ROWB 272
#define OFF_A0 0
#define OFF_A1 34816
#define OFF_B1 69632
#define OFF_B2 104448
#define OFF_B3 139264
#define OFF_IDX 174080
#define OFF_BIAS 175104
#define SZE 177152

// ---------------- dtype detection ----------------
__global__ void detect_kernel(const void* __restrict__ ei, long long E, int n) {
    const long long* p = (const long long*)ei;
    int ok64 = 1;
    int lim = (E < 64) ? (int)E : 64;
    for (int i = 0; i < lim; i++) {
        long long v = p[i];
        if (v < 0 || v >= n) { ok64 = 0; break; }
    }
    g_is64 = ok64;
}

__global__ void convert_kernel(const void* __restrict__ ei, long long E) {
    long long i = (long long)blockIdx.x * blockDim.x + threadIdx.x;
    if (i >= E) return;
    if (g_is64) {
        const long long* p = (const long long*)ei;
        g_src[i] = (int)p[i];
        g_dst[i] = (int)p[E + i];
    } else {
        const int* p = (const int*)ei;
        g_src[i] = p[i];
        g_dst[i] = p[E + i];
    }
}

// ---------------- zero z / num ----------------
__global__ void zero_kernel(int n) {
    int total = n * C;
    for (int i = (blockIdx.x * blockDim.x + threadIdx.x) * 4; i < total;
         i += gridDim.x * blockDim.x * 4) {
        *(float4*)&g_z[i] = make_float4(0.f, 0.f, 0.f, 0.f);
        *(float4*)&g_num[i] = make_float4(0.f, 0.f, 0.f, 0.f);
    }
}

// ---------------- Wq = W_dst@att_w1, Wk = W_src@att_w1 ----------------
__global__ void precombine_kernel(const float* __restrict__ Wdst,
                                  const float* __restrict__ Wsrc,
                                  const float* __restrict__ att_w1) {
    int r = blockIdx.x;
    int c = threadIdx.x;
    float aq = 0.f, ak = 0.f;
    for (int j = 0; j < C; j++) {
        float w1 = att_w1[j * C + c];
        aq += Wdst[r * C + j] * w1;
        ak += Wsrc[r * C + j] * w1;
    }
    g_Wq[r * C + c] = aq;
    g_Wk[r * C + c] = ak;
}

// ---------------- fp16 transposed weight prep ----------------
__global__ void wprep_kernel(const float* __restrict__ w1, const float* __restrict__ w2,
                             const float* __restrict__ w3) {
    int k = blockIdx.x, n = threadIdx.x;
    g_B1h[n * C + k] = __float2half_rn(w1[k * C + n]);
    g_B2h[n * C + k] = __float2half_rn(w2[k * C + n]);
    g_B3h[n * C + k] = __float2half_rn(w3[k * C + n]);
}

// ---------------- node kernel 1 ----------------
__global__ void __launch_bounds__(128, 1)
node1_kernel(const float* __restrict__ x, const float* __restrict__ pos,
             const float* __restrict__ W_in, const float* __restrict__ b_in,
             const float* __restrict__ pos_w1, int n) {
    extern __shared__ float sm[];
    float* sWin = sm;
    float* sWp1 = sm + C * C;
    float* sx = sm + 2 * C * C;
    float* sp = sm + 2 * C * C + 16 * C;
    float* sb = sm + 2 * C * C + 32 * C;

    int tid = threadIdx.x;
    for (int i = tid; i < C * C; i += 128) {
        sWin[i] = W_in[i];
        sWp1[i] = pos_w1[i];
    }
    if (tid < C) sb[tid] = b_in[tid];
    __syncthreads();

    int cg = tid & 31, ng = tid >> 5;
    int nbase = blockIdx.x * 16 + ng * 4;
#pragma unroll
    for (int i = 0; i < 4; i++) {
        int nn = nbase + i;
        if (nn < n) {
            ((float4*)&sx[(ng * 4 + i) * C])[cg] = ((const float4*)&x[(size_t)nn * C])[cg];
            ((float4*)&sp[(ng * 4 + i) * C])[cg] = ((const float4*)&pos[(size_t)nn * C])[cg];
        }
    }
    __syncwarp();

    float4 ah[4], ap[4];
#pragma unroll
    for (int i = 0; i < 4; i++) {
        ah[i] = make_float4(0.f, 0.f, 0.f, 0.f);
        ap[i] = make_float4(0.f, 0.f, 0.f, 0.f);
    }
#pragma unroll 2
    for (int k = 0; k < C; k++) {
        float4 wi = ((float4*)sWin)[k * 32 + cg];
        float4 wp = ((float4*)sWp1)[k * 32 + cg];
#pragma unroll
        for (int i = 0; i < 4; i++) {
            float xv = sx[(ng * 4 + i) * C + k];
            float pv = sp[(ng * 4 + i) * C + k];
            ah[i].x += xv * wi.x; ah[i].y += xv * wi.y;
            ah[i].z += xv * wi.z; ah[i].w += xv * wi.w;
            ap[i].x += pv * wp.x; ap[i].y += pv * wp.y;
            ap[i].z += pv * wp.z; ap[i].w += pv * wp.w;
        }
    }
    float4 bv = ((float4*)sb)[cg];
#pragma unroll
    for (int i = 0; i < 4; i++) {
        int nn = nbase + i;
        if (nn < n) {
            float4 hv;
            hv.x = fmaxf(ah[i].x + bv.x, 0.f);
            hv.y = fmaxf(ah[i].y + bv.y, 0.f);
            hv.z = fmaxf(ah[i].z + bv.z, 0.f);
            hv.w = fmaxf(ah[i].w + bv.w, 0.f);
            ((float4*)&g_h[(size_t)nn * C])[cg] = hv;
            ((float4*)&g_P1[(size_t)nn * C])[cg] = ap[i];
        }
    }
}

// ---------------- node kernel 2 ----------------
__global__ void __launch_bounds__(128, 1)
node2_kernel(const float* __restrict__ W_lin, int n) {
    extern __shared__ float sm[];
    float* sWl = sm;
    float* sWq = sm + C * C;
    float* sWk = sm + 2 * C * C;
    float* sh = sm + 3 * C * C;

    int tid = threadIdx.x;
    for (int i = tid; i < C * C; i += 128) {
        sWl[i] = W_lin[i];
        sWq[i] = g_Wq[i];
        sWk[i] = g_Wk[i];
    }
    __syncthreads();

    int cg = tid & 31, ng = tid >> 5;
    int nbase = blockIdx.x * 16 + ng * 4;
#pragma unroll
    for (int i = 0; i < 4; i++) {
        int nn = nbase + i;
        if (nn < n)
            ((float4*)&sh[(ng * 4 + i) * C])[cg] = ((const float4*)&g_h[(size_t)nn * C])[cg];
    }
    __syncwarp();

    float4 av[4], aq[4], ak[4];
#pragma unroll
    for (int i = 0; i < 4; i++) {
        av[i] = make_float4(0.f, 0.f, 0.f, 0.f);
        aq[i] = make_float4(0.f, 0.f, 0.f, 0.f);
        ak[i] = make_float4(0.f, 0.f, 0.f, 0.f);
    }
#pragma unroll 2
    for (int k = 0; k < C; k++) {
        float4 wl = ((float4*)sWl)[k * 32 + cg];
        float4 wq = ((float4*)sWq)[k * 32 + cg];
        float4 wk = ((float4*)sWk)[k * 32 + cg];
#pragma unroll
        for (int i = 0; i < 4; i++) {
            float hv = sh[(ng * 4 + i) * C + k];
            av[i].x += hv * wl.x; av[i].y += hv * wl.y; av[i].z += hv * wl.z; av[i].w += hv * wl.w;
            aq[i].x += hv * wq.x; aq[i].y += hv * wq.y; aq[i].z += hv * wq.z; aq[i].w += hv * wq.w;
            ak[i].x += hv * wk.x; ak[i].y += hv * wk.y; ak[i].z += hv * wk.z; ak[i].w += hv * wk.w;
        }
    }
#pragma unroll
    for (int i = 0; i < 4; i++) {
        int nn = nbase + i;
        if (nn < n) {
            ((float4*)&g_v[(size_t)nn * C])[cg] = av[i];
            ((float4*)&g_QK[(size_t)nn * C])[cg] = aq[i];
            ((float4*)&g_KK[(size_t)nn * C])[cg] = ak[i];
        }
    }
}

// ---------------- tensor-core edge kernel (mma.sync m16n8k16) ----------------
// 128 edges/tile, 256 threads = 8 warps. Warp w owns output cols [16w, 16w+16).
__global__ void __launch_bounds__(256, 1)
edge_mma_kernel(long long E,
                const float* __restrict__ pos_b1, const float* __restrict__ pos_b2,
                const float* __restrict__ att_b1, const float* __restrict__ att_b2) {
    extern __shared__ char smem[];
    uint32_t sbase = smem_u32(smem);
    int tid = threadIdx.x, wid = tid >> 5, lane = tid & 31;

    // weights -> smem [n][k] fp16, row stride ROWB
    for (int i = tid; i < C * C; i += 256) {
        int n = i >> 7, k = i & 127;
        uint32_t o = n * ROWB + k * 2;
        *(__half*)(smem + OFF_B1 + o) = g_B1h[i];
        *(__half*)(smem + OFF_B2 + o) = g_B2h[i];
        *(__half*)(smem + OFF_B3 + o) = g_B3h[i];
    }
    float* sBias = (float*)(smem + OFF_BIAS);
    if (tid < C) {
        sBias[tid] = pos_b1[tid];
        sBias[C + tid] = pos_b2[tid];
        sBias[2 * C + tid] = att_b1[tid];
        sBias[3 * C + tid] = att_b2[tid];
    }
    int* sSrc = (int*)(smem + OFF_IDX);
    int* sDst = sSrc + 128;
    __syncthreads();

    const int nbw = wid * 16;
    const int qr = lane >> 2;       // quad row 0..7
    const int qc = 2 * (lane & 3);  // col pair base 0,2,4,6

    // ldmatrix lane-address components
    const int lr = lane & 7;
    const int lg = lane >> 3;  // 0..3

    float acc[8][2][4];

    for (long long tile = blockIdx.x; tile * 128 < E; tile += gridDim.x) {
        long long ebase = tile * 128;
        if (tid < 128) {
            long long e = ebase + tid;
            sSrc[tid] = (e < E) ? g_src[e] : 0;
        } else {
            long long e = ebase + tid - 128;
            sDst[tid - 128] = (e < E) ? g_dst[e] : 0;
        }
        __syncthreads();

        // ---- stage G: A0 = relu(P1[dst]-P1[src]+pos_b1), fp16 [row][k] ----
        {
            float4 bp = ((float4*)sBias)[lane];
#pragma unroll 4
            for (int i = 0; i < 16; i++) {
                int e = wid * 16 + i;
                int s = sSrc[e], d = sDst[e];
                float4 pd = ((const float4*)(g_P1 + (size_t)d * C))[lane];
                float4 ps = ((const float4*)(g_P1 + (size_t)s * C))[lane];
                __half2 h0 = __floats2half2_rn(fmaxf(pd.x - ps.x + bp.x, 0.f),
                                               fmaxf(pd.y - ps.y + bp.y, 0.f));
                __half2 h1 = __floats2half2_rn(fmaxf(pd.z - ps.z + bp.z, 0.f),
                                               fmaxf(pd.w - ps.w + bp.w, 0.f));
                uint2 m;
                m.x = *(unsigned*)&h0;
                m.y = *(unsigned*)&h1;
                *(uint2*)(smem + OFF_A0 + e * ROWB + lane * 8) = m;
            }
        }
        __syncthreads();

        // ================= GEMM1: D = A0 @ B1^T =================
        {
            uint32_t bf[2][8][2];
#pragma unroll
            for (int nt = 0; nt < 2; nt++)
#pragma unroll
                for (int kt = 0; kt < 8; kt++) {
                    uint32_t a = sbase + OFF_B1 + (nbw + nt * 8 + lr) * ROWB +
                                 kt * 32 + (lg & 1) * 16;
                    ldsm_x2(a, bf[nt][kt][0], bf[nt][kt][1]);
                }
#pragma unroll
            for (int mt = 0; mt < 8; mt++)
#pragma unroll
                for (int nt = 0; nt < 2; nt++)
#pragma unroll
                    for (int j = 0; j < 4; j++) acc[mt][nt][j] = 0.f;
#pragma unroll 2
            for (int kt = 0; kt < 8; kt++) {
#pragma unroll
                for (int mt = 0; mt < 8; mt++) {
                    uint32_t a0, a1, a2, a3;
                    uint32_t ad = sbase + OFF_A0 +
                                  (mt * 16 + ((lg & 1) << 3) + lr) * ROWB +
                                  (kt * 16 + ((lg >> 1) << 3)) * 2;
                    ldsm_x4(ad, a0, a1, a2, a3);
                    mma_16816(acc[mt][0], a0, a1, a2, a3, bf[0][kt][0], bf[0][kt][1]);
                    mma_16816(acc[mt][1], a0, a1, a2, a3, bf[1][kt][0], bf[1][kt][1]);
                }
            }
        }

        // ---- E1: delta = relu(D + pos_b2) -> A1 fp16 ----
#pragma unroll
        for (int mt = 0; mt < 8; mt++) {
            int r0 = mt * 16 + qr, r1 = r0 + 8;
#pragma unroll
            for (int nt = 0; nt < 2; nt++) {
                int cb = nbw + nt * 8 + qc;
                float b0 = sBias[C + cb], b1 = sBias[C + cb + 1];
                float* d = acc[mt][nt];
                __half2 h0 = __floats2half2_rn(fmaxf(d[0] + b0, 0.f), fmaxf(d[1] + b1, 0.f));
                __half2 h1 = __floats2half2_rn(fmaxf(d[2] + b0, 0.f), fmaxf(d[3] + b1, 0.f));
                *(__half2*)(smem + OFF_A1 + r0 * ROWB + cb * 2) = h0;
                *(__half2*)(smem + OFF_A1 + r1 * ROWB + cb * 2) = h1;
            }
        }
        __syncthreads();

        // ================= GEMM2: D = A1 @ B2^T =================
        {
            uint32_t bf[2][8][2];
#pragma unroll
            for (int nt = 0; nt < 2; nt++)
#pragma unroll
                for (int kt = 0; kt < 8; kt++) {
                    uint32_t a = sbase + OFF_B2 + (nbw + nt * 8 + lr) * ROWB +
                                 kt * 32 + (lg & 1) * 16;
                    ldsm_x2(a, bf[nt][kt][0], bf[nt][kt][1]);
                }
#pragma unroll
            for (int mt = 0; mt < 8; mt++)
#pragma unroll
                for (int nt = 0; nt < 2; nt++)
#pragma unroll
                    for (int j = 0; j < 4; j++) acc[mt][nt][j] = 0.f;
#pragma unroll 2
            for (int kt = 0; kt < 8; kt++) {
#pragma unroll
                for (int mt = 0; mt < 8; mt++) {
                    uint32_t a0, a1, a2, a3;
                    uint32_t ad = sbase + OFF_A1 +
                                  (mt * 16 + ((lg & 1) << 3) + lr) * ROWB +
                                  (kt * 16 + ((lg >> 1) << 3)) * 2;
                    ldsm_x4(ad, a0, a1, a2, a3);
                    mma_16816(acc[mt][0], a0, a1, a2, a3, bf[0][kt][0], bf[0][kt][1]);
                    mma_16816(acc[mt][1], a0, a1, a2, a3, bf[1][kt][0], bf[1][kt][1]);
                }
            }
        }
        __syncthreads();  // A0 readers done (GEMM1), safe to overwrite below

        // ---- E2: t2 = relu(QK[dst]-KK[src] + D + att_b1) -> A0 fp16 ----
#pragma unroll
        for (int mt = 0; mt < 8; mt++) {
            int r0 = mt * 16 + qr, r1 = r0 + 8;
            int d0i = sDst[r0], s0i = sSrc[r0];
            int d1i = sDst[r1], s1i = sSrc[r1];
#pragma unroll
            for (int nt = 0; nt < 2; nt++) {
                int cb = nbw + nt * 8 + qc;
                float b0 = sBias[2 * C + cb], b1 = sBias[2 * C + cb + 1];
                float* d = acc[mt][nt];
                float2 q0 = *(const float2*)(g_QK + (size_t)d0i * C + cb);
                float2 k0 = *(const float2*)(g_KK + (size_t)s0i * C + cb);
                float2 q1 = *(const float2*)(g_QK + (size_t)d1i * C + cb);
                float2 k1 = *(const float2*)(g_KK + (size_t)s1i * C + cb);
                __half2 h0 = __floats2half2_rn(fmaxf(q0.x - k0.x + d[0] + b0, 0.f),
                                               fmaxf(q0.y - k0.y + d[1] + b1, 0.f));
                __half2 h1 = __floats2half2_rn(fmaxf(q1.x - k1.x + d[2] + b0, 0.f),
                                               fmaxf(q1.y - k1.y + d[3] + b1, 0.f));
                *(__half2*)(smem + OFF_A0 + r0 * ROWB + cb * 2) = h0;
                *(__half2*)(smem + OFF_A0 + r1 * ROWB + cb * 2) = h1;
            }
        }
        __syncthreads();

        // ================= GEMM3: D = A0(t2) @ B3^T =================
        {
            uint32_t bf[2][8][2];
#pragma unroll
            for (int nt = 0; nt < 2; nt++)
#pragma unroll
                for (int kt = 0; kt < 8; kt++) {
                    uint32_t a = sbase + OFF_B3 + (nbw + nt * 8 + lr) * ROWB +
                                 kt * 32 + (lg & 1) * 16;
                    ldsm_x2(a, bf[nt][kt][0], bf[nt][kt][1]);
                }
#pragma unroll
            for (int mt = 0; mt < 8; mt++)
#pragma unroll
                for (int nt = 0; nt < 2; nt++)
#pragma unroll
                    for (int j = 0; j < 4; j++) acc[mt][nt][j] = 0.f;
#pragma unroll 2
            for (int kt = 0; kt < 8; kt++) {
#pragma unroll
                for (int mt = 0; mt < 8; mt++) {
                    uint32_t a0, a1, a2, a3;
                    uint32_t ad = sbase + OFF_A0 +
                                  (mt * 16 + ((lg & 1) << 3) + lr) * ROWB +
                                  (kt * 16 + ((lg >> 1) << 3)) * 2;
                    ldsm_x4(ad, a0, a1, a2, a3);
                    mma_16816(acc[mt][0], a0, a1, a2, a3, bf[0][kt][0], bf[0][kt][1]);
                    mma_16816(acc[mt][1], a0, a1, a2, a3, bf[1][kt][0], bf[1][kt][1]);
                }
            }
        }

        // ---- E3: ez = exp(relu(D+att_b2)); nm = ez*(v[src]+delta); atomics ----
#pragma unroll
        for (int mt = 0; mt < 8; mt++) {
            int r0 = mt * 16 + qr, r1 = r0 + 8;
            int d0i = sDst[r0], s0i = sSrc[r0];
            int d1i = sDst[r1], s1i = sSrc[r1];
            bool v0 = (ebase + r0) < E, v1 = (ebase + r1) < E;
#pragma unroll
            for (int nt = 0; nt < 2; nt++) {
                int cb = nbw + nt * 8 + qc;
                float b0 = sBias[3 * C + cb], b1 = sBias[3 * C + cb + 1];
                float* d = acc[mt][nt];
                if (v0) {
                    float2 vv = *(const float2*)(g_v + (size_t)s0i * C + cb);
                    __half2 dh = *(__half2*)(smem + OFF_A1 + r0 * ROWB + cb * 2);
                    float2 df = __half22float2(dh);
                    float2 ez, nm;
                    ez.x = __expf(fmaxf(d[0] + b0, 0.f));
                    ez.y = __expf(fmaxf(d[1] + b1, 0.f));
                    nm.x = ez.x * (vv.x + df.x);
                    nm.y = ez.y * (vv.y + df.y);
                    atomicAdd((float2*)&g_z[(size_t)d0i * C + cb], ez);
                    atomicAdd((float2*)&g_num[(size_t)d0i * C + cb], nm);
                }
                if (v1) {
                    float2 vv = *(const float2*)(g_v + (size_t)s1i * C + cb);
                    __half2 dh = *(__half2*)(smem + OFF_A1 + r1 * ROWB + cb * 2);
                    float2 df = __half22float2(dh);
                    float2 ez, nm;
                    ez.x = __expf(fmaxf(d[2] + b0, 0.f));
                    ez.y = __expf(fmaxf(d[3] + b1, 0.f));
                    nm.x = ez.x * (vv.x + df.x);
                    nm.y = ez.y * (vv.y + df.y);
                    atomicAdd((float2*)&g_z[(size_t)d1i * C + cb], ez);
                    atomicAdd((float2*)&g_num[(size_t)d1i * C + cb], nm);
                }
            }
        }
        __syncthreads();
    }
}

// ---------------- out kernel ----------------
__global__ void __launch_bounds__(128, 1)
out_kernel(const float* __restrict__ W_out, const float* __restrict__ b_out,
           float* __restrict__ out, int n) {
    extern __shared__ float sm[];
    float* sW = sm;
    float* srow = sm + C * C;
    float* sb = sm + C * C + 16 * C;

    int tid = threadIdx.x;
    for (int i = tid; i < C * C; i += 128) sW[i] = W_out[i];
    if (tid < C) sb[tid] = b_out[tid];
    __syncthreads();

    int cg = tid & 31, ng = tid >> 5;
    int nbase = blockIdx.x * 16 + ng * 4;
#pragma unroll
    for (int i = 0; i < 4; i++) {
        int nn = nbase + i;
        if (nn < n) {
            float4 nm = ((const float4*)&g_num[(size_t)nn * C])[cg];
            float4 zz = ((const float4*)&g_z[(size_t)nn * C])[cg];
            float4 ag;
            ag.x = nm.x / (zz.x + 1e-16f);
            ag.y = nm.y / (zz.y + 1e-16f);
            ag.z = nm.z / (zz.z + 1e-16f);
            ag.w = nm.w / (zz.w + 1e-16f);
            ((float4*)&srow[(ng * 4 + i) * C])[cg] = ag;
        }
    }
    __syncwarp();

    float4 acc[4];
#pragma unroll
    for (int i = 0; i < 4; i++) acc[i] = make_float4(0.f, 0.f, 0.f, 0.f);
#pragma unroll 2
    for (int k = 0; k < C; k++) {
        float4 w = ((float4*)sW)[k * 32 + cg];
#pragma unroll
        for (int i = 0; i < 4; i++) {
            float av = srow[(ng * 4 + i) * C + k];
            acc[i].x += av * w.x; acc[i].y += av * w.y;
            acc[i].z += av * w.z; acc[i].w += av * w.w;
        }
    }
    float4 bv = ((float4*)sb)[cg];
#pragma unroll
    for (int i = 0; i < 4; i++) {
        int nn = nbase + i;
        if (nn < n) {
            float4 ov;
            ov.x = fmaxf(acc[i].x + bv.x, 0.f);
            ov.y = fmaxf(acc[i].y + bv.y, 0.f);
            ov.z = fmaxf(acc[i].z + bv.z, 0.f);
            ov.w = fmaxf(acc[i].w + bv.w, 0.f);
            ((float4*)&out[(size_t)nn * C])[cg] = ov;
        }
    }
}

// ---------------- launch ----------------
extern "C" void kernel_launch(void* const* d_in, const int* in_sizes, int n_in,
                              void* d_out, int out_size) {
    const float* x = (const float*)d_in[0];
    const float* pos = (const float*)d_in[1];
    const void* ei = d_in[2];
    const float* W_in = (const float*)d_in[3];
    const float* b_in = (const float*)d_in[4];
    const float* W_lin = (const float*)d_in[5];
    const float* W_src = (const float*)d_in[6];
    const float* W_dst = (const float*)d_in[7];
    const float* pos_w1 = (const float*)d_in[8];
    const float* pos_b1 = (const float*)d_in[9];
    const float* pos_w2 = (const float*)d_in[10];
    const float* pos_b2 = (const float*)d_in[11];
    const float* att_w1 = (const float*)d_in[12];
    const float* att_b1 = (const float*)d_in[13];
    const float* att_w2 = (const float*)d_in[14];
    const float* att_b2 = (const float*)d_in[15];
    const float* W_out = (const float*)d_in[16];
    const float* b_out = (const float*)d_in[17];

    int n = in_sizes[0] / C;
    long long E = in_sizes[2] / 2;

    const int SZ1 = (2 * C * C + 32 * C + C) * 4;
    const int SZ2 = (3 * C * C + 16 * C) * 4;
    const int SZO = (C * C + 16 * C + C) * 4;

    cudaFuncSetAttribute(node1_kernel, cudaFuncAttributeMaxDynamicSharedMemorySize, SZ1);
    cudaFuncSetAttribute(node2_kernel, cudaFuncAttributeMaxDynamicSharedMemorySize, SZ2);
    cudaFuncSetAttribute(edge_mma_kernel, cudaFuncAttributeMaxDynamicSharedMemorySize, SZE);
    cudaFuncSetAttribute(out_kernel, cudaFuncAttributeMaxDynamicSharedMemorySize, SZO);

    detect_kernel<<<1, 1>>>(ei, E, n);
    convert_kernel<<<(int)((E + 255) / 256), 256>>>(ei, E);

    zero_kernel<<<512, 256>>>(n);
    precombine_kernel<<<C, C>>>(W_dst, W_src, att_w1);
    wprep_kernel<<<C, C>>>(pos_w2, att_w1, att_w2);

    int nb = (n + 15) / 16;
    node1_kernel<<<nb, 128, SZ1>>>(x, pos, W_in, b_in, pos_w1, n);
    node2_kernel<<<nb, 128, SZ2>>>(W_lin, n);

    edge_mma_kernel<<<296, 256, SZE>>>(E, pos_b1, pos_b2, att_b1, att_b2);

    out_kernel<<<nb, 128, SZO>>>(W_out, b_out, (float*)d_out, n);
}

// round 8
// speedup vs baseline: 1.6756x; 1.1464x over previous
#include <cuda_runtime.h>
#include <cuda_fp16.h>
#include <cstdint>

#define C 128
#define NMAX 50176
#define EMAX 800000

// ---------------- device scratch ----------------
__device__ float g_P1[NMAX * C];
__device__ float g_QK[NMAX * C];
__device__ float g_KK[NMAX * C];
__device__ float g_v[NMAX * C];
__device__ float g_z[NMAX * C];
__device__ float g_num[NMAX * C];
__device__ float g_Wq[C * C];
__device__ float g_Wk[C * C];
__device__ int g_src[EMAX];
__device__ int g_dst[EMAX];
// fp16 transposed edge-GEMM weights: B[n][k] = W[k][n]
__device__ __half g_B1h[C * C];   // pos_w2^T
__device__ __half g_B2h[C * C];   // att_w1^T
__device__ __half g_B3h[C * C];   // att_w2^T

// ---------------- mma helpers (base-target sm_80+ instructions only) ----------------
__device__ __forceinline__ uint32_t smem_u32(const void* p) {
    uint32_t a;
    asm("{ .reg .u64 t; cvta.to.shared.u64 t, %1; cvt.u32.u64 %0, t; }" : "=r"(a) : "l"(p));
    return a;
}
__device__ __forceinline__ void ldsm_x4(uint32_t addr, uint32_t& r0, uint32_t& r1,
                                        uint32_t& r2, uint32_t& r3) {
    asm volatile("ldmatrix.sync.aligned.m8n8.x4.shared.b16 {%0,%1,%2,%3}, [%4];"
                 : "=r"(r0), "=r"(r1), "=r"(r2), "=r"(r3) : "r"(addr));
}
__device__ __forceinline__ void ldsm_x2(uint32_t addr, uint32_t& r0, uint32_t& r1) {
    asm volatile("ldmatrix.sync.aligned.m8n8.x2.shared.b16 {%0,%1}, [%2];"
                 : "=r"(r0), "=r"(r1) : "r"(addr));
}
__device__ __forceinline__ void mma_16816(float* acc, uint32_t a0, uint32_t a1,
                                          uint32_t a2, uint32_t a3,
                                          uint32_t b0, uint32_t b1) {
    asm volatile(
        "mma.sync.aligned.m16n8k16.row.col.f32.f16.f16.f32 "
        "{%0,%1,%2,%3}, {%4,%5,%6,%7}, {%8,%9}, {%0,%1,%2,%3};"
        : "+f"(acc[0]), "+f"(acc[1]), "+f"(acc[2]), "+f"(acc[3])
        : "r"(a0), "r"(a1), "r"(a2), "r"(a3), "r"(b0), "r"(b1));
}

// smem layout (bytes). Rows padded to 272B (136 halfs) -> conflict-free ldmatrix.
#define ROWB 272
#define OFF_A0 0
#define OFF_A1 34816
#define OFF_B1 69632
#define OFF_B2 104448
#define OFF_B3 139264
#define OFF_IDX 174080
#define OFF_BIAS 175104
#define SZE 177152

// ---------------- convert (with inlined dtype detection) ----------------
__global__ void convert_kernel(const void* __restrict__ ei, long long E, int n) {
    __shared__ int s_is64;
    if (threadIdx.x == 0) {
        const long long* p = (const long long*)ei;
        int ok64 = 1;
        int lim = (E < 64) ? (int)E : 64;
        for (int i = 0; i < lim; i++) {
            long long v = p[i];
            if (v < 0 || v >= n) { ok64 = 0; break; }
        }
        s_is64 = ok64;
    }
    __syncthreads();
    long long i = (long long)blockIdx.x * blockDim.x + threadIdx.x;
    if (i >= E) return;
    if (s_is64) {
        const long long* p = (const long long*)ei;
        g_src[i] = (int)p[i];
        g_dst[i] = (int)p[E + i];
    } else {
        const int* p = (const int*)ei;
        g_src[i] = p[i];
        g_dst[i] = p[E + i];
    }
}

// ---------------- util: zero z/num + precombine Wq/Wk + fp16 weight prep ----------------
__global__ void util_kernel(const float* __restrict__ Wdst, const float* __restrict__ Wsrc,
                            const float* __restrict__ att_w1,
                            const float* __restrict__ w1, const float* __restrict__ w2,
                            const float* __restrict__ w3, int n) {
    int total = n * C;
    for (int i = (blockIdx.x * 256 + threadIdx.x) * 4; i < total; i += gridDim.x * 256 * 4) {
        *(float4*)&g_z[i] = make_float4(0.f, 0.f, 0.f, 0.f);
        *(float4*)&g_num[i] = make_float4(0.f, 0.f, 0.f, 0.f);
    }
    if (blockIdx.x < C) {
        int r = blockIdx.x;
        if (threadIdx.x < C) {
            int c = threadIdx.x;
            float aq = 0.f, ak = 0.f;
            for (int j = 0; j < C; j++) {
                float w = att_w1[j * C + c];
                aq += Wdst[r * C + j] * w;
                ak += Wsrc[r * C + j] * w;
            }
            g_Wq[r * C + c] = aq;
            g_Wk[r * C + c] = ak;
        } else {
            int nn = threadIdx.x - C;  // 0..127
            g_B1h[nn * C + r] = __float2half_rn(w1[r * C + nn]);
            g_B2h[nn * C + r] = __float2half_rn(w2[r * C + nn]);
            g_B3h[nn * C + r] = __float2half_rn(w3[r * C + nn]);
        }
    }
}

// ---------------- fused node kernel: phase A h/P1, phase B v/QK/KK ----------------
// 256 threads, 32 nodes/block. smem 213504 B.
#define SZ12 213504
__global__ void __launch_bounds__(256, 1)
node12_kernel(const float* __restrict__ x, const float* __restrict__ pos,
              const float* __restrict__ W_in, const float* __restrict__ b_in,
              const float* __restrict__ pos_w1, const float* __restrict__ W_lin, int n) {
    extern __shared__ float sm[];
    float* W0 = sm;              // 16384 (A: W_in, B: W_lin)
    float* W1 = sm + 16384;      // 16384 (A: pos_w1, B: Wq)
    float* W2 = sm + 32768;      // 16384 (B: Wk); phase A reuses for sx/sp
    float* sx = sm + 32768;      // 4096
    float* sp = sm + 36864;      // 4096
    float* sh = sm + 49152;      // 4096 (persists A->B)
    float* sb = sm + 53248;      // 128

    int tid = threadIdx.x;
    for (int i = tid; i < C * C; i += 256) {
        W0[i] = W_in[i];
        W1[i] = pos_w1[i];
    }
    if (tid < C) sb[tid] = b_in[tid];
    __syncthreads();

    int cg = tid & 31, ng = tid >> 5;
    int nbase = blockIdx.x * 32 + ng * 4;

    // ---- phase A: h = relu(x@W_in+b_in) -> sh; P1 = pos@pos_w1 -> gmem ----
#pragma unroll
    for (int i = 0; i < 4; i++) {
        int nn = nbase + i;
        if (nn < n) {
            ((float4*)&sx[(ng * 4 + i) * C])[cg] = ((const float4*)&x[(size_t)nn * C])[cg];
            ((float4*)&sp[(ng * 4 + i) * C])[cg] = ((const float4*)&pos[(size_t)nn * C])[cg];
        }
    }
    __syncwarp();

    {
        float4 ah[4], ap[4];
#pragma unroll
        for (int i = 0; i < 4; i++) {
            ah[i] = make_float4(0.f, 0.f, 0.f, 0.f);
            ap[i] = make_float4(0.f, 0.f, 0.f, 0.f);
        }
#pragma unroll 2
        for (int k = 0; k < C; k++) {
            float4 wi = ((float4*)W0)[k * 32 + cg];
            float4 wp = ((float4*)W1)[k * 32 + cg];
#pragma unroll
            for (int i = 0; i < 4; i++) {
                float xv = sx[(ng * 4 + i) * C + k];
                float pv = sp[(ng * 4 + i) * C + k];
                ah[i].x += xv * wi.x; ah[i].y += xv * wi.y;
                ah[i].z += xv * wi.z; ah[i].w += xv * wi.w;
                ap[i].x += pv * wp.x; ap[i].y += pv * wp.y;
                ap[i].z += pv * wp.z; ap[i].w += pv * wp.w;
            }
        }
        float4 bv = ((float4*)sb)[cg];
#pragma unroll
        for (int i = 0; i < 4; i++) {
            int nn = nbase + i;
            float4 hv;
            hv.x = fmaxf(ah[i].x + bv.x, 0.f);
            hv.y = fmaxf(ah[i].y + bv.y, 0.f);
            hv.z = fmaxf(ah[i].z + bv.z, 0.f);
            hv.w = fmaxf(ah[i].w + bv.w, 0.f);
            ((float4*)&sh[(ng * 4 + i) * C])[cg] = hv;
            if (nn < n) ((float4*)&g_P1[(size_t)nn * C])[cg] = ap[i];
        }
    }
    __syncthreads();

    // ---- phase B: v = h@W_lin; QK = h@Wq; KK = h@Wk ----
    for (int i = tid; i < C * C; i += 256) {
        W0[i] = W_lin[i];
        W1[i] = g_Wq[i];
        W2[i] = g_Wk[i];
    }
    __syncthreads();

    float4 av[4], aq[4], ak[4];
#pragma unroll
    for (int i = 0; i < 4; i++) {
        av[i] = make_float4(0.f, 0.f, 0.f, 0.f);
        aq[i] = make_float4(0.f, 0.f, 0.f, 0.f);
        ak[i] = make_float4(0.f, 0.f, 0.f, 0.f);
    }
#pragma unroll 2
    for (int k = 0; k < C; k++) {
        float4 wl = ((float4*)W0)[k * 32 + cg];
        float4 wq = ((float4*)W1)[k * 32 + cg];
        float4 wk = ((float4*)W2)[k * 32 + cg];
#pragma unroll
        for (int i = 0; i < 4; i++) {
            float hv = sh[(ng * 4 + i) * C + k];
            av[i].x += hv * wl.x; av[i].y += hv * wl.y; av[i].z += hv * wl.z; av[i].w += hv * wl.w;
            aq[i].x += hv * wq.x; aq[i].y += hv * wq.y; aq[i].z += hv * wq.z; aq[i].w += hv * wq.w;
            ak[i].x += hv * wk.x; ak[i].y += hv * wk.y; ak[i].z += hv * wk.z; ak[i].w += hv * wk.w;
        }
    }
#pragma unroll
    for (int i = 0; i < 4; i++) {
        int nn = nbase + i;
        if (nn < n) {
            ((float4*)&g_v[(size_t)nn * C])[cg] = av[i];
            ((float4*)&g_QK[(size_t)nn * C])[cg] = aq[i];
            ((float4*)&g_KK[(size_t)nn * C])[cg] = ak[i];
        }
    }
}

// ---------------- tensor-core edge kernel (mma.sync m16n8k16) ----------------
// 128 edges/tile, 256 threads = 8 warps. Warp w owns output cols [16w, 16w+16).
__global__ void __launch_bounds__(256, 1)
edge_mma_kernel(long long E,
                const float* __restrict__ pos_b1, const float* __restrict__ pos_b2,
                const float* __restrict__ att_b1, const float* __restrict__ att_b2) {
    extern __shared__ char smem[];
    uint32_t sbase = smem_u32(smem);
    int tid = threadIdx.x, wid = tid >> 5, lane = tid & 31;

    // weights -> smem [n][k] fp16, row stride ROWB
    for (int i = tid; i < C * C; i += 256) {
        int n = i >> 7, k = i & 127;
        uint32_t o = n * ROWB + k * 2;
        *(__half*)(smem + OFF_B1 + o) = g_B1h[i];
        *(__half*)(smem + OFF_B2 + o) = g_B2h[i];
        *(__half*)(smem + OFF_B3 + o) = g_B3h[i];
    }
    float* sBias = (float*)(smem + OFF_BIAS);
    if (tid < C) {
        sBias[tid] = pos_b1[tid];
        sBias[C + tid] = pos_b2[tid];
        sBias[2 * C + tid] = att_b1[tid];
        sBias[3 * C + tid] = att_b2[tid];
    }
    int* sSrc = (int*)(smem + OFF_IDX);
    int* sDst = sSrc + 128;
    __syncthreads();

    const int nbw = wid * 16;
    const int qr = lane >> 2;       // quad row 0..7
    const int qc = 2 * (lane & 3);  // col pair base 0,2,4,6

    // ldmatrix lane-address components
    const int lr = lane & 7;
    const int lg = lane >> 3;  // 0..3

    float acc[8][2][4];

    for (long long tile = blockIdx.x; tile * 128 < E; tile += gridDim.x) {
        long long ebase = tile * 128;
        if (tid < 128) {
            long long e = ebase + tid;
            sSrc[tid] = (e < E) ? g_src[e] : 0;
        } else {
            long long e = ebase + tid - 128;
            sDst[tid - 128] = (e < E) ? g_dst[e] : 0;
        }
        __syncthreads();

        // ---- stage G: A0 = relu(P1[dst]-P1[src]+pos_b1), fp16 [row][k] ----
        {
            float4 bp = ((float4*)sBias)[lane];
#pragma unroll 4
            for (int i = 0; i < 16; i++) {
                int e = wid * 16 + i;
                int s = sSrc[e], d = sDst[e];
                float4 pd = ((const float4*)(g_P1 + (size_t)d * C))[lane];
                float4 ps = ((const float4*)(g_P1 + (size_t)s * C))[lane];
                __half2 h0 = __floats2half2_rn(fmaxf(pd.x - ps.x + bp.x, 0.f),
                                               fmaxf(pd.y - ps.y + bp.y, 0.f));
                __half2 h1 = __floats2half2_rn(fmaxf(pd.z - ps.z + bp.z, 0.f),
                                               fmaxf(pd.w - ps.w + bp.w, 0.f));
                uint2 m;
                m.x = *(unsigned*)&h0;
                m.y = *(unsigned*)&h1;
                *(uint2*)(smem + OFF_A0 + e * ROWB + lane * 8) = m;
            }
        }
        __syncthreads();

        // ================= GEMM1: D = A0 @ B1^T =================
        {
            uint32_t bf[2][8][2];
#pragma unroll
            for (int nt = 0; nt < 2; nt++)
#pragma unroll
                for (int kt = 0; kt < 8; kt++) {
                    uint32_t a = sbase + OFF_B1 + (nbw + nt * 8 + lr) * ROWB +
                                 kt * 32 + (lg & 1) * 16;
                    ldsm_x2(a, bf[nt][kt][0], bf[nt][kt][1]);
                }
#pragma unroll
            for (int mt = 0; mt < 8; mt++)
#pragma unroll
                for (int nt = 0; nt < 2; nt++)
#pragma unroll
                    for (int j = 0; j < 4; j++) acc[mt][nt][j] = 0.f;
#pragma unroll 2
            for (int kt = 0; kt < 8; kt++) {
#pragma unroll
                for (int mt = 0; mt < 8; mt++) {
                    uint32_t a0, a1, a2, a3;
                    uint32_t ad = sbase + OFF_A0 +
                                  (mt * 16 + ((lg & 1) << 3) + lr) * ROWB +
                                  (kt * 16 + ((lg >> 1) << 3)) * 2;
                    ldsm_x4(ad, a0, a1, a2, a3);
                    mma_16816(acc[mt][0], a0, a1, a2, a3, bf[0][kt][0], bf[0][kt][1]);
                    mma_16816(acc[mt][1], a0, a1, a2, a3, bf[1][kt][0], bf[1][kt][1]);
                }
            }
        }

        // ---- E1: delta = relu(D + pos_b2) -> A1 fp16 ----
#pragma unroll
        for (int mt = 0; mt < 8; mt++) {
            int r0 = mt * 16 + qr, r1 = r0 + 8;
#pragma unroll
            for (int nt = 0; nt < 2; nt++) {
                int cb = nbw + nt * 8 + qc;
                float b0 = sBias[C + cb], b1 = sBias[C + cb + 1];
                float* d = acc[mt][nt];
                __half2 h0 = __floats2half2_rn(fmaxf(d[0] + b0, 0.f), fmaxf(d[1] + b1, 0.f));
                __half2 h1 = __floats2half2_rn(fmaxf(d[2] + b0, 0.f), fmaxf(d[3] + b1, 0.f));
                *(__half2*)(smem + OFF_A1 + r0 * ROWB + cb * 2) = h0;
                *(__half2*)(smem + OFF_A1 + r1 * ROWB + cb * 2) = h1;
            }
        }
        __syncthreads();

        // ================= GEMM2: D = A1 @ B2^T =================
        {
            uint32_t bf[2][8][2];
#pragma unroll
            for (int nt = 0; nt < 2; nt++)
#pragma unroll
                for (int kt = 0; kt < 8; kt++) {
                    uint32_t a = sbase + OFF_B2 + (nbw + nt * 8 + lr) * ROWB +
                                 kt * 32 + (lg & 1) * 16;
                    ldsm_x2(a, bf[nt][kt][0], bf[nt][kt][1]);
                }
#pragma unroll
            for (int mt = 0; mt < 8; mt++)
#pragma unroll
                for (int nt = 0; nt < 2; nt++)
#pragma unroll
                    for (int j = 0; j < 4; j++) acc[mt][nt][j] = 0.f;
#pragma unroll 2
            for (int kt = 0; kt < 8; kt++) {
#pragma unroll
                for (int mt = 0; mt < 8; mt++) {
                    uint32_t a0, a1, a2, a3;
                    uint32_t ad = sbase + OFF_A1 +
                                  (mt * 16 + ((lg & 1) << 3) + lr) * ROWB +
                                  (kt * 16 + ((lg >> 1) << 3)) * 2;
                    ldsm_x4(ad, a0, a1, a2, a3);
                    mma_16816(acc[mt][0], a0, a1, a2, a3, bf[0][kt][0], bf[0][kt][1]);
                    mma_16816(acc[mt][1], a0, a1, a2, a3, bf[1][kt][0], bf[1][kt][1]);
                }
            }
        }
        __syncthreads();  // A0 readers done (GEMM1), safe to overwrite below

        // ---- E2: t2 = relu(QK[dst]-KK[src] + D + att_b1) -> A0 fp16 ----
#pragma unroll
        for (int mt = 0; mt < 8; mt++) {
            int r0 = mt * 16 + qr, r1 = r0 + 8;
            int d0i = sDst[r0], s0i = sSrc[r0];
            int d1i = sDst[r1], s1i = sSrc[r1];
#pragma unroll
            for (int nt = 0; nt < 2; nt++) {
                int cb = nbw + nt * 8 + qc;
                float b0 = sBias[2 * C + cb], b1 = sBias[2 * C + cb + 1];
                float* d = acc[mt][nt];
                float2 q0 = *(const float2*)(g_QK + (size_t)d0i * C + cb);
                float2 k0 = *(const float2*)(g_KK + (size_t)s0i * C + cb);
                float2 q1 = *(const float2*)(g_QK + (size_t)d1i * C + cb);
                float2 k1 = *(const float2*)(g_KK + (size_t)s1i * C + cb);
                __half2 h0 = __floats2half2_rn(fmaxf(q0.x - k0.x + d[0] + b0, 0.f),
                                               fmaxf(q0.y - k0.y + d[1] + b1, 0.f));
                __half2 h1 = __floats2half2_rn(fmaxf(q1.x - k1.x + d[2] + b0, 0.f),
                                               fmaxf(q1.y - k1.y + d[3] + b1, 0.f));
                *(__half2*)(smem + OFF_A0 + r0 * ROWB + cb * 2) = h0;
                *(__half2*)(smem + OFF_A0 + r1 * ROWB + cb * 2) = h1;
            }
        }
        __syncthreads();

        // ================= GEMM3: D = A0(t2) @ B3^T =================
        {
            uint32_t bf[2][8][2];
#pragma unroll
            for (int nt = 0; nt < 2; nt++)
#pragma unroll
                for (int kt = 0; kt < 8; kt++) {
                    uint32_t a = sbase + OFF_B3 + (nbw + nt * 8 + lr) * ROWB +
                                 kt * 32 + (lg & 1) * 16;
                    ldsm_x2(a, bf[nt][kt][0], bf[nt][kt][1]);
                }
#pragma unroll
            for (int mt = 0; mt < 8; mt++)
#pragma unroll
                for (int nt = 0; nt < 2; nt++)
#pragma unroll
                    for (int j = 0; j < 4; j++) acc[mt][nt][j] = 0.f;
#pragma unroll 2
            for (int kt = 0; kt < 8; kt++) {
#pragma unroll
                for (int mt = 0; mt < 8; mt++) {
                    uint32_t a0, a1, a2, a3;
                    uint32_t ad = sbase + OFF_A0 +
                                  (mt * 16 + ((lg & 1) << 3) + lr) * ROWB +
                                  (kt * 16 + ((lg >> 1) << 3)) * 2;
                    ldsm_x4(ad, a0, a1, a2, a3);
                    mma_16816(acc[mt][0], a0, a1, a2, a3, bf[0][kt][0], bf[0][kt][1]);
                    mma_16816(acc[mt][1], a0, a1, a2, a3, bf[1][kt][0], bf[1][kt][1]);
                }
            }
        }

        // ---- E3: ez = exp(relu(D+att_b2)); nm = ez*(v[src]+delta); atomics ----
#pragma unroll
        for (int mt = 0; mt < 8; mt++) {
            int r0 = mt * 16 + qr, r1 = r0 + 8;
            int d0i = sDst[r0], s0i = sSrc[r0];
            int d1i = sDst[r1], s1i = sSrc[r1];
            bool v0 = (ebase + r0) < E, v1 = (ebase + r1) < E;
#pragma unroll
            for (int nt = 0; nt < 2; nt++) {
                int cb = nbw + nt * 8 + qc;
                float b0 = sBias[3 * C + cb], b1 = sBias[3 * C + cb + 1];
                float* d = acc[mt][nt];
                if (v0) {
                    float2 vv = *(const float2*)(g_v + (size_t)s0i * C + cb);
                    __half2 dh = *(__half2*)(smem + OFF_A1 + r0 * ROWB + cb * 2);
                    float2 df = __half22float2(dh);
                    float2 ez, nm;
                    ez.x = __expf(fmaxf(d[0] + b0, 0.f));
                    ez.y = __expf(fmaxf(d[1] + b1, 0.f));
                    nm.x = ez.x * (vv.x + df.x);
                    nm.y = ez.y * (vv.y + df.y);
                    atomicAdd((float2*)&g_z[(size_t)d0i * C + cb], ez);
                    atomicAdd((float2*)&g_num[(size_t)d0i * C + cb], nm);
                }
                if (v1) {
                    float2 vv = *(const float2*)(g_v + (size_t)s1i * C + cb);
                    __half2 dh = *(__half2*)(smem + OFF_A1 + r1 * ROWB + cb * 2);
                    float2 df = __half22float2(dh);
                    float2 ez, nm;
                    ez.x = __expf(fmaxf(d[2] + b0, 0.f));
                    ez.y = __expf(fmaxf(d[3] + b1, 0.f));
                    nm.x = ez.x * (vv.x + df.x);
                    nm.y = ez.y * (vv.y + df.y);
                    atomicAdd((float2*)&g_z[(size_t)d1i * C + cb], ez);
                    atomicAdd((float2*)&g_num[(size_t)d1i * C + cb], nm);
                }
            }
        }
        __syncthreads();
    }
}

// ---------------- out kernel: 256 threads, 32 nodes/block, 2 CTA/SM ----------------
#define SZO2 ((C * C + 32 * C + C) * 4)
__global__ void __launch_bounds__(256, 2)
out_kernel(const float* __restrict__ W_out, const float* __restrict__ b_out,
           float* __restrict__ out, int n) {
    extern __shared__ float sm[];
    float* sW = sm;
    float* srow = sm + C * C;
    float* sb = sm + C * C + 32 * C;

    int tid = threadIdx.x;
    for (int i = tid; i < C * C; i += 256) sW[i] = W_out[i];
    if (tid < C) sb[tid] = b_out[tid];
    __syncthreads();

    int cg = tid & 31, ng = tid >> 5;
    int nbase = blockIdx.x * 32 + ng * 4;
#pragma unroll
    for (int i = 0; i < 4; i++) {
        int nn = nbase + i;
        if (nn < n) {
            float4 nm = ((const float4*)&g_num[(size_t)nn * C])[cg];
            float4 zz = ((const float4*)&g_z[(size_t)nn * C])[cg];
            float4 ag;
            ag.x = nm.x / (zz.x + 1e-16f);
            ag.y = nm.y / (zz.y + 1e-16f);
            ag.z = nm.z / (zz.z + 1e-16f);
            ag.w = nm.w / (zz.w + 1e-16f);
            ((float4*)&srow[(ng * 4 + i) * C])[cg] = ag;
        } else {
            ((float4*)&srow[(ng * 4 + i) * C])[cg] = make_float4(0.f, 0.f, 0.f, 0.f);
        }
    }
    __syncwarp();

    float4 acc[4];
#pragma unroll
    for (int i = 0; i < 4; i++) acc[i] = make_float4(0.f, 0.f, 0.f, 0.f);
#pragma unroll 2
    for (int k = 0; k < C; k++) {
        float4 w = ((float4*)sW)[k * 32 + cg];
#pragma unroll
        for (int i = 0; i < 4; i++) {
            float av = srow[(ng * 4 + i) * C + k];
            acc[i].x += av * w.x; acc[i].y += av * w.y;
            acc[i].z += av * w.z; acc[i].w += av * w.w;
        }
    }
    float4 bv = ((float4*)sb)[cg];
#pragma unroll
    for (int i = 0; i < 4; i++) {
        int nn = nbase + i;
        if (nn < n) {
            float4 ov;
            ov.x = fmaxf(acc[i].x + bv.x, 0.f);
            ov.y = fmaxf(acc[i].y + bv.y, 0.f);
            ov.z = fmaxf(acc[i].z + bv.z, 0.f);
            ov.w = fmaxf(acc[i].w + bv.w, 0.f);
            ((float4*)&out[(size_t)nn * C])[cg] = ov;
        }
    }
}

// ---------------- launch ----------------
extern "C" void kernel_launch(void* const* d_in, const int* in_sizes, int n_in,
                              void* d_out, int out_size) {
    const float* x = (const float*)d_in[0];
    const float* pos = (const float*)d_in[1];
    const void* ei = d_in[2];
    const float* W_in = (const float*)d_in[3];
    const float* b_in = (const float*)d_in[4];
    const float* W_lin = (const float*)d_in[5];
    const float* W_src = (const float*)d_in[6];
    const float* W_dst = (const float*)d_in[7];
    const float* pos_w1 = (const float*)d_in[8];
    const float* pos_b1 = (const float*)d_in[9];
    const float* pos_w2 = (const float*)d_in[10];
    const float* pos_b2 = (const float*)d_in[11];
    const float* att_w1 = (const float*)d_in[12];
    const float* att_b1 = (const float*)d_in[13];
    const float* att_w2 = (const float*)d_in[14];
    const float* att_b2 = (const float*)d_in[15];
    const float* W_out = (const float*)d_in[16];
    const float* b_out = (const float*)d_in[17];

    int n = in_sizes[0] / C;
    long long E = in_sizes[2] / 2;

    cudaFuncSetAttribute(node12_kernel, cudaFuncAttributeMaxDynamicSharedMemorySize, SZ12);
    cudaFuncSetAttribute(edge_mma_kernel, cudaFuncAttributeMaxDynamicSharedMemorySize, SZE);
    cudaFuncSetAttribute(out_kernel, cudaFuncAttributeMaxDynamicSharedMemorySize, SZO2);

    convert_kernel<<<(int)((E + 255) / 256), 256>>>(ei, E, n);
    util_kernel<<<512, 256>>>(W_dst, W_src, att_w1, pos_w2, att_w1, att_w2, n);

    int nb = (n + 31) / 32;
    node12_kernel<<<nb, 256, SZ12>>>(x, pos, W_in, b_in, pos_w1, W_lin, n);

    edge_mma_kernel<<<148, 256, SZE>>>(E, pos_b1, pos_b2, att_b1, att_b2);

    out_kernel<<<nb, 256, SZO2>>>(W_out, b_out, (float*)d_out, n);
}

// round 9
// speedup vs baseline: 1.8914x; 1.1288x over previous
#include <cuda_runtime.h>
#include <cuda_fp16.h>
#include <cstdint>

#define C 128
#define NMAX 50176
#define EMAX 800000

// ---------------- device scratch ----------------
__device__ float g_P1[NMAX * C];
__device__ float g_QK[NMAX * C];
__device__ float g_KK[NMAX * C];
__device__ float g_v[NMAX * C];
__device__ float g_z[NMAX * C];
__device__ float g_num[NMAX * C];
__device__ float g_Wq[C * C];
__device__ float g_Wk[C * C];
__device__ int g_src[EMAX];
__device__ int g_dst[EMAX];
__device__ int g_src2[EMAX];   // sorted by dst
__device__ int g_dst2[EMAX];
__device__ int g_cnt[NMAX];    // histogram -> cursor
__device__ __half g_B1h[C * C];
__device__ __half g_B2h[C * C];
__device__ __half g_B3h[C * C];

// ---------------- mma helpers ----------------
__device__ __forceinline__ uint32_t smem_u32(const void* p) {
    uint32_t a;
    asm("{ .reg .u64 t; cvta.to.shared.u64 t, %1; cvt.u32.u64 %0, t; }" : "=r"(a) : "l"(p));
    return a;
}
__device__ __forceinline__ void ldsm_x4(uint32_t addr, uint32_t& r0, uint32_t& r1,
                                        uint32_t& r2, uint32_t& r3) {
    asm volatile("ldmatrix.sync.aligned.m8n8.x4.shared.b16 {%0,%1,%2,%3}, [%4];"
                 : "=r"(r0), "=r"(r1), "=r"(r2), "=r"(r3) : "r"(addr));
}
__device__ __forceinline__ void ldsm_x2(uint32_t addr, uint32_t& r0, uint32_t& r1) {
    asm volatile("ldmatrix.sync.aligned.m8n8.x2.shared.b16 {%0,%1}, [%2];"
                 : "=r"(r0), "=r"(r1) : "r"(addr));
}
__device__ __forceinline__ void mma_16816(float* acc, uint32_t a0, uint32_t a1,
                                          uint32_t a2, uint32_t a3,
                                          uint32_t b0, uint32_t b1) {
    asm volatile(
        "mma.sync.aligned.m16n8k16.row.col.f32.f16.f16.f32 "
        "{%0,%1,%2,%3}, {%4,%5,%6,%7}, {%8,%9}, {%0,%1,%2,%3};"
        : "+f"(acc[0]), "+f"(acc[1]), "+f"(acc[2]), "+f"(acc[3])
        : "r"(a0), "r"(a1), "r"(a2), "r"(a3), "r"(b0), "r"(b1));
}

// smem layout (bytes). fp16 tiles rows padded to 272B.
#define ROWB 272
#define OFF_A0 0
#define OFF_A1 34816
#define OFF_B1 69632
#define OFF_B2 104448
#define OFF_B3 139264
#define OFF_IDX 174080
#define OFF_BIAS 175104
#define OFF_S2 177152          // fp32 staging: 128 rows x 68 floats (272B)
#define SZE 211968

// ---------------- convert (dtype detect) + zero histogram ----------------
__global__ void convert_kernel(const void* __restrict__ ei, long long E, int n) {
    __shared__ int s_is64;
    if (threadIdx.x == 0) {
        const long long* p = (const long long*)ei;
        int ok64 = 1;
        int lim = (E < 64) ? (int)E : 64;
        for (int i = 0; i < lim; i++) {
            long long v = p[i];
            if (v < 0 || v >= n) { ok64 = 0; break; }
        }
        s_is64 = ok64;
    }
    __syncthreads();
    long long i = (long long)blockIdx.x * blockDim.x + threadIdx.x;
    if (i < n) g_cnt[i] = 0;
    if (i >= E) return;
    if (s_is64) {
        const long long* p = (const long long*)ei;
        g_src[i] = (int)p[i];
        g_dst[i] = (int)p[E + i];
    } else {
        const int* p = (const int*)ei;
        g_src[i] = p[i];
        g_dst[i] = p[E + i];
    }
}

// ---------------- counting sort: histogram / scan / scatter ----------------
__global__ void hist_kernel(long long E) {
    long long i = (long long)blockIdx.x * blockDim.x + threadIdx.x;
    if (i < E) atomicAdd(&g_cnt[g_dst[i]], 1);
}

__global__ void scan_kernel(int n) {
    __shared__ int part[1024];
    int t = threadIdx.x;
    int chunk = (n + 1023) / 1024;
    int lo = t * chunk;
    int hi = lo + chunk; if (hi > n) hi = n;
    int s = 0;
    for (int i = lo; i < hi; i++) s += g_cnt[i];
    part[t] = s;
    __syncthreads();
    for (int d = 1; d < 1024; d <<= 1) {
        int v = (t >= d) ? part[t - d] : 0;
        __syncthreads();
        part[t] += v;
        __syncthreads();
    }
    int excl = (t == 0) ? 0 : part[t - 1];
    for (int i = lo; i < hi; i++) {
        int c = g_cnt[i];
        g_cnt[i] = excl;   // becomes running cursor
        excl += c;
    }
}

__global__ void scatter_kernel(long long E) {
    long long i = (long long)blockIdx.x * blockDim.x + threadIdx.x;
    if (i >= E) return;
    int d = g_dst[i];
    int p = atomicAdd(&g_cnt[d], 1);
    g_src2[p] = g_src[i];
    g_dst2[p] = d;
}

// ---------------- util: zero z/num + precombine Wq/Wk + fp16 weight prep ----------------
__global__ void util_kernel(const float* __restrict__ Wdst, const float* __restrict__ Wsrc,
                            const float* __restrict__ att_w1,
                            const float* __restrict__ w1, const float* __restrict__ w2,
                            const float* __restrict__ w3, int n) {
    int total = n * C;
    for (int i = (blockIdx.x * 256 + threadIdx.x) * 4; i < total; i += gridDim.x * 256 * 4) {
        *(float4*)&g_z[i] = make_float4(0.f, 0.f, 0.f, 0.f);
        *(float4*)&g_num[i] = make_float4(0.f, 0.f, 0.f, 0.f);
    }
    if (blockIdx.x < C) {
        int r = blockIdx.x;
        if (threadIdx.x < C) {
            int c = threadIdx.x;
            float aq = 0.f, ak = 0.f;
            for (int j = 0; j < C; j++) {
                float w = att_w1[j * C + c];
                aq += Wdst[r * C + j] * w;
                ak += Wsrc[r * C + j] * w;
            }
            g_Wq[r * C + c] = aq;
            g_Wk[r * C + c] = ak;
        } else {
            int nn = threadIdx.x - C;
            g_B1h[nn * C + r] = __float2half_rn(w1[r * C + nn]);
            g_B2h[nn * C + r] = __float2half_rn(w2[r * C + nn]);
            g_B3h[nn * C + r] = __float2half_rn(w3[r * C + nn]);
        }
    }
}

// ---------------- fused node kernel ----------------
#define SZ12 213504
__global__ void __launch_bounds__(256, 1)
node12_kernel(const float* __restrict__ x, const float* __restrict__ pos,
              const float* __restrict__ W_in, const float* __restrict__ b_in,
              const float* __restrict__ pos_w1, const float* __restrict__ W_lin, int n) {
    extern __shared__ float sm[];
    float* W0 = sm;
    float* W1 = sm + 16384;
    float* W2 = sm + 32768;
    float* sx = sm + 32768;
    float* sp = sm + 36864;
    float* sh = sm + 49152;
    float* sb = sm + 53248;

    int tid = threadIdx.x;
    for (int i = tid; i < C * C; i += 256) {
        W0[i] = W_in[i];
        W1[i] = pos_w1[i];
    }
    if (tid < C) sb[tid] = b_in[tid];
    __syncthreads();

    int cg = tid & 31, ng = tid >> 5;
    int nbase = blockIdx.x * 32 + ng * 4;

#pragma unroll
    for (int i = 0; i < 4; i++) {
        int nn = nbase + i;
        if (nn < n) {
            ((float4*)&sx[(ng * 4 + i) * C])[cg] = ((const float4*)&x[(size_t)nn * C])[cg];
            ((float4*)&sp[(ng * 4 + i) * C])[cg] = ((const float4*)&pos[(size_t)nn * C])[cg];
        }
    }
    __syncwarp();

    {
        float4 ah[4], ap[4];
#pragma unroll
        for (int i = 0; i < 4; i++) {
            ah[i] = make_float4(0.f, 0.f, 0.f, 0.f);
            ap[i] = make_float4(0.f, 0.f, 0.f, 0.f);
        }
#pragma unroll 2
        for (int k = 0; k < C; k++) {
            float4 wi = ((float4*)W0)[k * 32 + cg];
            float4 wp = ((float4*)W1)[k * 32 + cg];
#pragma unroll
            for (int i = 0; i < 4; i++) {
                float xv = sx[(ng * 4 + i) * C + k];
                float pv = sp[(ng * 4 + i) * C + k];
                ah[i].x += xv * wi.x; ah[i].y += xv * wi.y;
                ah[i].z += xv * wi.z; ah[i].w += xv * wi.w;
                ap[i].x += pv * wp.x; ap[i].y += pv * wp.y;
                ap[i].z += pv * wp.z; ap[i].w += pv * wp.w;
            }
        }
        float4 bv = ((float4*)sb)[cg];
#pragma unroll
        for (int i = 0; i < 4; i++) {
            int nn = nbase + i;
            float4 hv;
            hv.x = fmaxf(ah[i].x + bv.x, 0.f);
            hv.y = fmaxf(ah[i].y + bv.y, 0.f);
            hv.z = fmaxf(ah[i].z + bv.z, 0.f);
            hv.w = fmaxf(ah[i].w + bv.w, 0.f);
            ((float4*)&sh[(ng * 4 + i) * C])[cg] = hv;
            if (nn < n) ((float4*)&g_P1[(size_t)nn * C])[cg] = ap[i];
        }
    }
    __syncthreads();

    for (int i = tid; i < C * C; i += 256) {
        W0[i] = W_lin[i];
        W1[i] = g_Wq[i];
        W2[i] = g_Wk[i];
    }
    __syncthreads();

    float4 av[4], aq[4], ak[4];
#pragma unroll
    for (int i = 0; i < 4; i++) {
        av[i] = make_float4(0.f, 0.f, 0.f, 0.f);
        aq[i] = make_float4(0.f, 0.f, 0.f, 0.f);
        ak[i] = make_float4(0.f, 0.f, 0.f, 0.f);
    }
#pragma unroll 2
    for (int k = 0; k < C; k++) {
        float4 wl = ((float4*)W0)[k * 32 + cg];
        float4 wq = ((float4*)W1)[k * 32 + cg];
        float4 wk = ((float4*)W2)[k * 32 + cg];
#pragma unroll
        for (int i = 0; i < 4; i++) {
            float hv = sh[(ng * 4 + i) * C + k];
            av[i].x += hv * wl.x; av[i].y += hv * wl.y; av[i].z += hv * wl.z; av[i].w += hv * wl.w;
            aq[i].x += hv * wq.x; aq[i].y += hv * wq.y; aq[i].z += hv * wq.z; aq[i].w += hv * wq.w;
            ak[i].x += hv * wk.x; ak[i].y += hv * wk.y; ak[i].z += hv * wk.z; ak[i].w += hv * wk.w;
        }
    }
#pragma unroll
    for (int i = 0; i < 4; i++) {
        int nn = nbase + i;
        if (nn < n) {
            ((float4*)&g_v[(size_t)nn * C])[cg] = av[i];
            ((float4*)&g_QK[(size_t)nn * C])[cg] = aq[i];
            ((float4*)&g_KK[(size_t)nn * C])[cg] = ak[i];
        }
    }
}

// ---------------- segment reduce helper (sorted dst) ----------------
__device__ __forceinline__ void seg_reduce(char* smem, const int* sDst, float* gbase,
                                           int hf, int tid) {
    if (tid < 256) {
        int p = tid & 31;        // channel pair within half
        int seg = tid >> 5;      // 8 segments x 16 edges
        int e0 = seg * 16;
        int chg = hf * 64 + p * 2;
        float2 s = make_float2(0.f, 0.f);
        int cur = sDst[e0];
#pragma unroll 4
        for (int i = 0; i < 16; i++) {
            int e = e0 + i;
            int d = sDst[e];
            if (d != cur) {
                if (cur >= 0) atomicAdd((float2*)(gbase + (size_t)cur * C + chg), s);
                s.x = 0.f; s.y = 0.f;
                cur = d;
            }
            float2 v = *(float2*)(smem + OFF_S2 + e * 272 + p * 8);
            s.x += v.x; s.y += v.y;
        }
        if (cur >= 0) atomicAdd((float2*)(gbase + (size_t)cur * C + chg), s);
    }
}

// ---------------- tensor-core edge kernel: 512 threads, sorted edges ----------------
__global__ void __launch_bounds__(512, 1)
edge_mma_kernel(long long E,
                const float* __restrict__ pos_b1, const float* __restrict__ pos_b2,
                const float* __restrict__ att_b1, const float* __restrict__ att_b2) {
    extern __shared__ char smem[];
    uint32_t sbase = smem_u32(smem);
    int tid = threadIdx.x, wid = tid >> 5, lane = tid & 31;

    for (int i = tid; i < C * C; i += 512) {
        int n = i >> 7, k = i & 127;
        uint32_t o = n * ROWB + k * 2;
        *(__half*)(smem + OFF_B1 + o) = g_B1h[i];
        *(__half*)(smem + OFF_B2 + o) = g_B2h[i];
        *(__half*)(smem + OFF_B3 + o) = g_B3h[i];
    }
    float* sBias = (float*)(smem + OFF_BIAS);
    if (tid < C) {
        sBias[tid] = pos_b1[tid];
        sBias[C + tid] = pos_b2[tid];
        sBias[2 * C + tid] = att_b1[tid];
        sBias[3 * C + tid] = att_b2[tid];
    }
    int* sSrc = (int*)(smem + OFF_IDX);
    int* sDst = sSrc + 128;
    __syncthreads();

    const int nbw = wid * 8;          // warp owns 8 output columns
    const int qr = lane >> 2;
    const int qc = 2 * (lane & 3);
    const int lr = lane & 7;
    const int lg = lane >> 3;
    const int cb = nbw + qc;

    float acc[8][4];
    uint32_t bf[8][2];

    for (long long tile = blockIdx.x; tile * 128 < E; tile += gridDim.x) {
        long long ebase = tile * 128;
        if (tid < 128) {
            sSrc[tid] = (ebase + tid < E) ? g_src2[ebase + tid] : 0;
        } else if (tid < 256) {
            int j = tid - 128;
            sDst[j] = (ebase + j < E) ? g_dst2[ebase + j] : -1;
        }
        __syncthreads();

        // ---- stage G: A0 = relu(P1[dst]-P1[src]+pos_b1) ----
        {
            float4 bp = ((float4*)sBias)[lane];
#pragma unroll 4
            for (int i = 0; i < 8; i++) {
                int e = wid * 8 + i;
                int s = sSrc[e];
                int d = sDst[e]; if (d < 0) d = 0;
                float4 pd = ((const float4*)(g_P1 + (size_t)d * C))[lane];
                float4 ps = ((const float4*)(g_P1 + (size_t)s * C))[lane];
                __half2 h0 = __floats2half2_rn(fmaxf(pd.x - ps.x + bp.x, 0.f),
                                               fmaxf(pd.y - ps.y + bp.y, 0.f));
                __half2 h1 = __floats2half2_rn(fmaxf(pd.z - ps.z + bp.z, 0.f),
                                               fmaxf(pd.w - ps.w + bp.w, 0.f));
                uint2 m;
                m.x = *(unsigned*)&h0;
                m.y = *(unsigned*)&h1;
                *(uint2*)(smem + OFF_A0 + e * ROWB + lane * 8) = m;
            }
        }
        __syncthreads();

#define GEMM(OFFB, OFFA)                                                            \
        {                                                                           \
            _Pragma("unroll")                                                       \
            for (int kt = 0; kt < 8; kt++) {                                        \
                uint32_t a = sbase + (OFFB) + (nbw + lr) * ROWB + kt * 32 +         \
                             (lg & 1) * 16;                                         \
                ldsm_x2(a, bf[kt][0], bf[kt][1]);                                   \
            }                                                                       \
            _Pragma("unroll")                                                       \
            for (int mt = 0; mt < 8; mt++)                                          \
                _Pragma("unroll")                                                   \
                for (int j = 0; j < 4; j++) acc[mt][j] = 0.f;                       \
            _Pragma("unroll 2")                                                     \
            for (int kt = 0; kt < 8; kt++) {                                        \
                _Pragma("unroll")                                                   \
                for (int mt = 0; mt < 8; mt++) {                                    \
                    uint32_t a0, a1, a2, a3;                                        \
                    uint32_t ad = sbase + (OFFA) +                                  \
                                  (mt * 16 + ((lg & 1) << 3) + lr) * ROWB +         \
                                  (kt * 16 + ((lg >> 1) << 3)) * 2;                 \
                    ldsm_x4(ad, a0, a1, a2, a3);                                    \
                    mma_16816(acc[mt], a0, a1, a2, a3, bf[kt][0], bf[kt][1]);       \
                }                                                                   \
            }                                                                       \
        }

        // ===== GEMM1: A0 @ B1^T =====
        GEMM(OFF_B1, OFF_A0)

        // ---- E1: delta = relu(D + pos_b2) -> A1 ----
        {
            float b0 = sBias[C + cb], b1 = sBias[C + cb + 1];
#pragma unroll
            for (int mt = 0; mt < 8; mt++) {
                int r0 = mt * 16 + qr, r1 = r0 + 8;
                __half2 h0 = __floats2half2_rn(fmaxf(acc[mt][0] + b0, 0.f),
                                               fmaxf(acc[mt][1] + b1, 0.f));
                __half2 h1 = __floats2half2_rn(fmaxf(acc[mt][2] + b0, 0.f),
                                               fmaxf(acc[mt][3] + b1, 0.f));
                *(__half2*)(smem + OFF_A1 + r0 * ROWB + cb * 2) = h0;
                *(__half2*)(smem + OFF_A1 + r1 * ROWB + cb * 2) = h1;
            }
        }
        __syncthreads();

        // ===== GEMM2: A1 @ B2^T =====
        GEMM(OFF_B2, OFF_A1)
        __syncthreads();

        // ---- E2: t2 = relu(QK[dst]-KK[src] + D + att_b1) -> A0 ----
        {
            float b0 = sBias[2 * C + cb], b1 = sBias[2 * C + cb + 1];
#pragma unroll
            for (int mt = 0; mt < 8; mt++) {
                int r0 = mt * 16 + qr, r1 = r0 + 8;
                int d0i = sDst[r0]; if (d0i < 0) d0i = 0;
                int s0i = sSrc[r0];
                int d1i = sDst[r1]; if (d1i < 0) d1i = 0;
                int s1i = sSrc[r1];
                float2 q0 = *(const float2*)(g_QK + (size_t)d0i * C + cb);
                float2 k0 = *(const float2*)(g_KK + (size_t)s0i * C + cb);
                float2 q1 = *(const float2*)(g_QK + (size_t)d1i * C + cb);
                float2 k1 = *(const float2*)(g_KK + (size_t)s1i * C + cb);
                __half2 h0 = __floats2half2_rn(fmaxf(q0.x - k0.x + acc[mt][0] + b0, 0.f),
                                               fmaxf(q0.y - k0.y + acc[mt][1] + b1, 0.f));
                __half2 h1 = __floats2half2_rn(fmaxf(q1.x - k1.x + acc[mt][2] + b0, 0.f),
                                               fmaxf(q1.y - k1.y + acc[mt][3] + b1, 0.f));
                *(__half2*)(smem + OFF_A0 + r0 * ROWB + cb * 2) = h0;
                *(__half2*)(smem + OFF_A0 + r1 * ROWB + cb * 2) = h1;
            }
        }
        __syncthreads();

        // ===== GEMM3: A0(t2) @ B3^T =====
        GEMM(OFF_B3, OFF_A0)

        // ---- ez = exp(relu(D + att_b2)) in place ----
        {
            float b0 = sBias[3 * C + cb], b1 = sBias[3 * C + cb + 1];
#pragma unroll
            for (int mt = 0; mt < 8; mt++) {
                acc[mt][0] = __expf(fmaxf(acc[mt][0] + b0, 0.f));
                acc[mt][1] = __expf(fmaxf(acc[mt][1] + b1, 0.f));
                acc[mt][2] = __expf(fmaxf(acc[mt][2] + b0, 0.f));
                acc[mt][3] = __expf(fmaxf(acc[mt][3] + b1, 0.f));
            }
        }

        // ---- nm passes: stage ez*(v[src]+delta) per 64-ch half, segment-reduce ----
#pragma unroll
        for (int hf = 0; hf < 2; hf++) {
            if ((wid >> 3) == hf) {
                int cbl = cb - hf * 64;
#pragma unroll
                for (int mt = 0; mt < 8; mt++) {
                    int r0 = mt * 16 + qr, r1 = r0 + 8;
                    int s0i = sSrc[r0], s1i = sSrc[r1];
                    float2 v0 = *(const float2*)(g_v + (size_t)s0i * C + cb);
                    float2 v1 = *(const float2*)(g_v + (size_t)s1i * C + cb);
                    float2 f0 = __half22float2(*(__half2*)(smem + OFF_A1 + r0 * ROWB + cb * 2));
                    float2 f1 = __half22float2(*(__half2*)(smem + OFF_A1 + r1 * ROWB + cb * 2));
                    float2 n0 = make_float2(acc[mt][0] * (v0.x + f0.x),
                                            acc[mt][1] * (v0.y + f0.y));
                    float2 n1 = make_float2(acc[mt][2] * (v1.x + f1.x),
                                            acc[mt][3] * (v1.y + f1.y));
                    *(float2*)(smem + OFF_S2 + r0 * 272 + cbl * 4) = n0;
                    *(float2*)(smem + OFF_S2 + r1 * 272 + cbl * 4) = n1;
                }
            }
            __syncthreads();
            seg_reduce(smem, sDst, g_num, hf, tid);
            __syncthreads();
        }

        // ---- ez passes ----
#pragma unroll
        for (int hf = 0; hf < 2; hf++) {
            if ((wid >> 3) == hf) {
                int cbl = cb - hf * 64;
#pragma unroll
                for (int mt = 0; mt < 8; mt++) {
                    int r0 = mt * 16 + qr, r1 = r0 + 8;
                    *(float2*)(smem + OFF_S2 + r0 * 272 + cbl * 4) =
                        make_float2(acc[mt][0], acc[mt][1]);
                    *(float2*)(smem + OFF_S2 + r1 * 272 + cbl * 4) =
                        make_float2(acc[mt][2], acc[mt][3]);
                }
            }
            __syncthreads();
            seg_reduce(smem, sDst, g_z, hf, tid);
            __syncthreads();
        }
    }
}

// ---------------- out kernel ----------------
#define SZO2 ((C * C + 32 * C + C) * 4)
__global__ void __launch_bounds__(256, 2)
out_kernel(const float* __restrict__ W_out, const float* __restrict__ b_out,
           float* __restrict__ out, int n) {
    extern __shared__ float sm[];
    float* sW = sm;
    float* srow = sm + C * C;
    float* sb = sm + C * C + 32 * C;

    int tid = threadIdx.x;
    for (int i = tid; i < C * C; i += 256) sW[i] = W_out[i];
    if (tid < C) sb[tid] = b_out[tid];
    __syncthreads();

    int cg = tid & 31, ng = tid >> 5;
    int nbase = blockIdx.x * 32 + ng * 4;
#pragma unroll
    for (int i = 0; i < 4; i++) {
        int nn = nbase + i;
        if (nn < n) {
            float4 nm = ((const float4*)&g_num[(size_t)nn * C])[cg];
            float4 zz = ((const float4*)&g_z[(size_t)nn * C])[cg];
            float4 ag;
            ag.x = nm.x / (zz.x + 1e-16f);
            ag.y = nm.y / (zz.y + 1e-16f);
            ag.z = nm.z / (zz.z + 1e-16f);
            ag.w = nm.w / (zz.w + 1e-16f);
            ((float4*)&srow[(ng * 4 + i) * C])[cg] = ag;
        } else {
            ((float4*)&srow[(ng * 4 + i) * C])[cg] = make_float4(0.f, 0.f, 0.f, 0.f);
        }
    }
    __syncwarp();

    float4 acc[4];
#pragma unroll
    for (int i = 0; i < 4; i++) acc[i] = make_float4(0.f, 0.f, 0.f, 0.f);
#pragma unroll 2
    for (int k = 0; k < C; k++) {
        float4 w = ((float4*)sW)[k * 32 + cg];
#pragma unroll
        for (int i = 0; i < 4; i++) {
            float av = srow[(ng * 4 + i) * C + k];
            acc[i].x += av * w.x; acc[i].y += av * w.y;
            acc[i].z += av * w.z; acc[i].w += av * w.w;
        }
    }
    float4 bv = ((float4*)sb)[cg];
#pragma unroll
    for (int i = 0; i < 4; i++) {
        int nn = nbase + i;
        if (nn < n) {
            float4 ov;
            ov.x = fmaxf(acc[i].x + bv.x, 0.f);
            ov.y = fmaxf(acc[i].y + bv.y, 0.f);
            ov.z = fmaxf(acc[i].z + bv.z, 0.f);
            ov.w = fmaxf(acc[i].w + bv.w, 0.f);
            ((float4*)&out[(size_t)nn * C])[cg] = ov;
        }
    }
}

// ---------------- launch ----------------
extern "C" void kernel_launch(void* const* d_in, const int* in_sizes, int n_in,
                              void* d_out, int out_size) {
    const float* x = (const float*)d_in[0];
    const float* pos = (const float*)d_in[1];
    const void* ei = d_in[2];
    const float* W_in = (const float*)d_in[3];
    const float* b_in = (const float*)d_in[4];
    const float* W_lin = (const float*)d_in[5];
    const float* W_src = (const float*)d_in[6];
    const float* W_dst = (const float*)d_in[7];
    const float* pos_w1 = (const float*)d_in[8];
    const float* pos_b1 = (const float*)d_in[9];
    const float* pos_w2 = (const float*)d_in[10];
    const float* pos_b2 = (const float*)d_in[11];
    const float* att_w1 = (const float*)d_in[12];
    const float* att_b1 = (const float*)d_in[13];
    const float* att_w2 = (const float*)d_in[14];
    const float* att_b2 = (const float*)d_in[15];
    const float* W_out = (const float*)d_in[16];
    const float* b_out = (const float*)d_in[17];

    int n = in_sizes[0] / C;
    long long E = in_sizes[2] / 2;
    int eb = (int)((E + 255) / 256);

    cudaFuncSetAttribute(node12_kernel, cudaFuncAttributeMaxDynamicSharedMemorySize, SZ12);
    cudaFuncSetAttribute(edge_mma_kernel, cudaFuncAttributeMaxDynamicSharedMemorySize, SZE);
    cudaFuncSetAttribute(out_kernel, cudaFuncAttributeMaxDynamicSharedMemorySize, SZO2);

    convert_kernel<<<eb, 256>>>(ei, E, n);
    hist_kernel<<<eb, 256>>>(E);
    scan_kernel<<<1, 1024>>>(n);
    scatter_kernel<<<eb, 256>>>(E);

    util_kernel<<<512, 256>>>(W_dst, W_src, att_w1, pos_w2, att_w1, att_w2, n);

    int nb = (n + 31) / 32;
    node12_kernel<<<nb, 256, SZ12>>>(x, pos, W_in, b_in, pos_w1, W_lin, n);

    edge_mma_kernel<<<148, 512, SZE>>>(E, pos_b1, pos_b2, att_b1, att_b2);

    out_kernel<<<nb, 256, SZO2>>>(W_out, b_out, (float*)d_out, n);
}

// round 10
// speedup vs baseline: 2.2579x; 1.1938x over previous
#include <cuda_runtime.h>
#include <cuda_fp16.h>
#include <cstdint>

#define C 128
#define NMAX 50176
#define EMAX 800000

// ---------------- device scratch ----------------
__device__ float g_P1[NMAX * C];
__device__ float g_QK[NMAX * C];
__device__ float g_KK[NMAX * C];
__device__ float g_v[NMAX * C];
__device__ float g_z[NMAX * C];
__device__ float g_num[NMAX * C];
__device__ float g_Wq[C * C];
__device__ float g_Wk[C * C];
__device__ int g_src[EMAX];
__device__ int g_dst[EMAX];
__device__ int g_src2[EMAX];   // sorted by dst
__device__ int g_dst2[EMAX];
__device__ int g_cnt[NMAX];    // histogram -> cursor
__device__ __half g_B1h[C * C];
__device__ __half g_B2h[C * C];
__device__ __half g_B3h[C * C];

// ---------------- mma helpers ----------------
__device__ __forceinline__ uint32_t smem_u32(const void* p) {
    uint32_t a;
    asm("{ .reg .u64 t; cvta.to.shared.u64 t, %1; cvt.u32.u64 %0, t; }" : "=r"(a) : "l"(p));
    return a;
}
__device__ __forceinline__ void ldsm_x4(uint32_t addr, uint32_t& r0, uint32_t& r1,
                                        uint32_t& r2, uint32_t& r3) {
    asm volatile("ldmatrix.sync.aligned.m8n8.x4.shared.b16 {%0,%1,%2,%3}, [%4];"
                 : "=r"(r0), "=r"(r1), "=r"(r2), "=r"(r3) : "r"(addr));
}
__device__ __forceinline__ void ldsm_x2(uint32_t addr, uint32_t& r0, uint32_t& r1) {
    asm volatile("ldmatrix.sync.aligned.m8n8.x2.shared.b16 {%0,%1}, [%2];"
                 : "=r"(r0), "=r"(r1) : "r"(addr));
}
__device__ __forceinline__ void mma_16816(float* acc, uint32_t a0, uint32_t a1,
                                          uint32_t a2, uint32_t a3,
                                          uint32_t b0, uint32_t b1) {
    asm volatile(
        "mma.sync.aligned.m16n8k16.row.col.f32.f16.f16.f32 "
        "{%0,%1,%2,%3}, {%4,%5,%6,%7}, {%8,%9}, {%0,%1,%2,%3};"
        : "+f"(acc[0]), "+f"(acc[1]), "+f"(acc[2]), "+f"(acc[3])
        : "r"(a0), "r"(a1), "r"(a2), "r"(a3), "r"(b0), "r"(b1));
}
#define PF_L2(ptr) asm volatile("prefetch.global.L2 [%0];" :: "l"(ptr))

// smem layout (bytes). fp16 tiles rows padded to 272B.
#define ROWB 272
#define OFF_A0 0               // also reused as staging buffer (hf=1) post-GEMM3
#define OFF_A1 34816
#define OFF_B1 69632
#define OFF_B2 104448
#define OFF_B3 139264
#define OFF_IDX 174080
#define OFF_BIAS 175104
#define OFF_S2 177152          // fp32 staging (hf=0): 128 rows x 272B
#define SZE 211968

// ---------------- convert (dtype detect) + zero histogram ----------------
__global__ void convert_kernel(const void* __restrict__ ei, long long E, int n) {
    __shared__ int s_is64;
    if (threadIdx.x == 0) {
        const long long* p = (const long long*)ei;
        int ok64 = 1;
        int lim = (E < 64) ? (int)E : 64;
        for (int i = 0; i < lim; i++) {
            long long v = p[i];
            if (v < 0 || v >= n) { ok64 = 0; break; }
        }
        s_is64 = ok64;
    }
    __syncthreads();
    long long i = (long long)blockIdx.x * blockDim.x + threadIdx.x;
    if (i < n) g_cnt[i] = 0;
    if (i >= E) return;
    if (s_is64) {
        const long long* p = (const long long*)ei;
        g_src[i] = (int)p[i];
        g_dst[i] = (int)p[E + i];
    } else {
        const int* p = (const int*)ei;
        g_src[i] = p[i];
        g_dst[i] = p[E + i];
    }
}

// ---------------- counting sort ----------------
__global__ void hist_kernel(long long E) {
    long long i = (long long)blockIdx.x * blockDim.x + threadIdx.x;
    if (i < E) atomicAdd(&g_cnt[g_dst[i]], 1);
}

__global__ void scan_kernel(int n) {
    __shared__ int part[1024];
    int t = threadIdx.x;
    int chunk = (n + 1023) / 1024;
    int lo = t * chunk;
    int hi = lo + chunk; if (hi > n) hi = n;
    int s = 0;
    for (int i = lo; i < hi; i++) s += g_cnt[i];
    part[t] = s;
    __syncthreads();
    for (int d = 1; d < 1024; d <<= 1) {
        int v = (t >= d) ? part[t - d] : 0;
        __syncthreads();
        part[t] += v;
        __syncthreads();
    }
    int excl = (t == 0) ? 0 : part[t - 1];
    for (int i = lo; i < hi; i++) {
        int c = g_cnt[i];
        g_cnt[i] = excl;
        excl += c;
    }
}

__global__ void scatter_kernel(long long E) {
    long long i = (long long)blockIdx.x * blockDim.x + threadIdx.x;
    if (i >= E) return;
    int d = g_dst[i];
    int p = atomicAdd(&g_cnt[d], 1);
    g_src2[p] = g_src[i];
    g_dst2[p] = d;
}

// ---------------- util ----------------
__global__ void util_kernel(const float* __restrict__ Wdst, const float* __restrict__ Wsrc,
                            const float* __restrict__ att_w1,
                            const float* __restrict__ w1, const float* __restrict__ w2,
                            const float* __restrict__ w3, int n) {
    int total = n * C;
    for (int i = (blockIdx.x * 256 + threadIdx.x) * 4; i < total; i += gridDim.x * 256 * 4) {
        *(float4*)&g_z[i] = make_float4(0.f, 0.f, 0.f, 0.f);
        *(float4*)&g_num[i] = make_float4(0.f, 0.f, 0.f, 0.f);
    }
    if (blockIdx.x < C) {
        int r = blockIdx.x;
        if (threadIdx.x < C) {
            int c = threadIdx.x;
            float aq = 0.f, ak = 0.f;
            for (int j = 0; j < C; j++) {
                float w = att_w1[j * C + c];
                aq += Wdst[r * C + j] * w;
                ak += Wsrc[r * C + j] * w;
            }
            g_Wq[r * C + c] = aq;
            g_Wk[r * C + c] = ak;
        } else {
            int nn = threadIdx.x - C;
            g_B1h[nn * C + r] = __float2half_rn(w1[r * C + nn]);
            g_B2h[nn * C + r] = __float2half_rn(w2[r * C + nn]);
            g_B3h[nn * C + r] = __float2half_rn(w3[r * C + nn]);
        }
    }
}

// ---------------- fused node kernel ----------------
#define SZ12 213504
__global__ void __launch_bounds__(256, 1)
node12_kernel(const float* __restrict__ x, const float* __restrict__ pos,
              const float* __restrict__ W_in, const float* __restrict__ b_in,
              const float* __restrict__ pos_w1, const float* __restrict__ W_lin, int n) {
    extern __shared__ float sm[];
    float* W0 = sm;
    float* W1 = sm + 16384;
    float* W2 = sm + 32768;
    float* sx = sm + 32768;
    float* sp = sm + 36864;
    float* sh = sm + 49152;
    float* sb = sm + 53248;

    int tid = threadIdx.x;
    for (int i = tid; i < C * C; i += 256) {
        W0[i] = W_in[i];
        W1[i] = pos_w1[i];
    }
    if (tid < C) sb[tid] = b_in[tid];
    __syncthreads();

    int cg = tid & 31, ng = tid >> 5;
    int nbase = blockIdx.x * 32 + ng * 4;

#pragma unroll
    for (int i = 0; i < 4; i++) {
        int nn = nbase + i;
        if (nn < n) {
            ((float4*)&sx[(ng * 4 + i) * C])[cg] = ((const float4*)&x[(size_t)nn * C])[cg];
            ((float4*)&sp[(ng * 4 + i) * C])[cg] = ((const float4*)&pos[(size_t)nn * C])[cg];
        }
    }
    __syncwarp();

    {
        float4 ah[4], ap[4];
#pragma unroll
        for (int i = 0; i < 4; i++) {
            ah[i] = make_float4(0.f, 0.f, 0.f, 0.f);
            ap[i] = make_float4(0.f, 0.f, 0.f, 0.f);
        }
#pragma unroll 2
        for (int k = 0; k < C; k++) {
            float4 wi = ((float4*)W0)[k * 32 + cg];
            float4 wp = ((float4*)W1)[k * 32 + cg];
#pragma unroll
            for (int i = 0; i < 4; i++) {
                float xv = sx[(ng * 4 + i) * C + k];
                float pv = sp[(ng * 4 + i) * C + k];
                ah[i].x += xv * wi.x; ah[i].y += xv * wi.y;
                ah[i].z += xv * wi.z; ah[i].w += xv * wi.w;
                ap[i].x += pv * wp.x; ap[i].y += pv * wp.y;
                ap[i].z += pv * wp.z; ap[i].w += pv * wp.w;
            }
        }
        float4 bv = ((float4*)sb)[cg];
#pragma unroll
        for (int i = 0; i < 4; i++) {
            int nn = nbase + i;
            float4 hv;
            hv.x = fmaxf(ah[i].x + bv.x, 0.f);
            hv.y = fmaxf(ah[i].y + bv.y, 0.f);
            hv.z = fmaxf(ah[i].z + bv.z, 0.f);
            hv.w = fmaxf(ah[i].w + bv.w, 0.f);
            ((float4*)&sh[(ng * 4 + i) * C])[cg] = hv;
            if (nn < n) ((float4*)&g_P1[(size_t)nn * C])[cg] = ap[i];
        }
    }
    __syncthreads();

    for (int i = tid; i < C * C; i += 256) {
        W0[i] = W_lin[i];
        W1[i] = g_Wq[i];
        W2[i] = g_Wk[i];
    }
    __syncthreads();

    float4 av[4], aq[4], ak[4];
#pragma unroll
    for (int i = 0; i < 4; i++) {
        av[i] = make_float4(0.f, 0.f, 0.f, 0.f);
        aq[i] = make_float4(0.f, 0.f, 0.f, 0.f);
        ak[i] = make_float4(0.f, 0.f, 0.f, 0.f);
    }
#pragma unroll 2
    for (int k = 0; k < C; k++) {
        float4 wl = ((float4*)W0)[k * 32 + cg];
        float4 wq = ((float4*)W1)[k * 32 + cg];
        float4 wk = ((float4*)W2)[k * 32 + cg];
#pragma unroll
        for (int i = 0; i < 4; i++) {
            float hv = sh[(ng * 4 + i) * C + k];
            av[i].x += hv * wl.x; av[i].y += hv * wl.y; av[i].z += hv * wl.z; av[i].w += hv * wl.w;
            aq[i].x += hv * wq.x; aq[i].y += hv * wq.y; aq[i].z += hv * wq.z; aq[i].w += hv * wq.w;
            ak[i].x += hv * wk.x; ak[i].y += hv * wk.y; ak[i].z += hv * wk.z; ak[i].w += hv * wk.w;
        }
    }
#pragma unroll
    for (int i = 0; i < 4; i++) {
        int nn = nbase + i;
        if (nn < n) {
            ((float4*)&g_v[(size_t)nn * C])[cg] = av[i];
            ((float4*)&g_QK[(size_t)nn * C])[cg] = aq[i];
            ((float4*)&g_KK[(size_t)nn * C])[cg] = ak[i];
        }
    }
}

// ---------------- full-block segment reduce (both halves at once) ----------------
__device__ __forceinline__ void seg_reduce2(char* smem, const int* sDst, float* gbase,
                                            int tid) {
    int p = tid & 31;            // channel pair within half
    int hf = (tid >> 5) & 1;     // which 64-channel half
    int seg = tid >> 6;          // 8 segments x 16 edges
    int e0 = seg * 16;
    int chg = hf * 64 + p * 2;
    int bufoff = hf ? OFF_A0 : OFF_S2;
    float2 s = make_float2(0.f, 0.f);
    int cur = sDst[e0];
#pragma unroll 4
    for (int i = 0; i < 16; i++) {
        int e = e0 + i;
        int d = sDst[e];
        if (d != cur) {
            if (cur >= 0) atomicAdd((float2*)(gbase + (size_t)cur * C + chg), s);
            s.x = 0.f; s.y = 0.f;
            cur = d;
        }
        float2 v = *(float2*)(smem + bufoff + e * ROWB + p * 8);
        s.x += v.x; s.y += v.y;
    }
    if (cur >= 0) atomicAdd((float2*)(gbase + (size_t)cur * C + chg), s);
}

// ---------------- tensor-core edge kernel: 512 threads, sorted, prefetch ----------------
__global__ void __launch_bounds__(512, 1)
edge_mma_kernel(long long E,
                const float* __restrict__ pos_b1, const float* __restrict__ pos_b2,
                const float* __restrict__ att_b1, const float* __restrict__ att_b2) {
    extern __shared__ char smem[];
    uint32_t sbase = smem_u32(smem);
    int tid = threadIdx.x, wid = tid >> 5, lane = tid & 31;

    for (int i = tid; i < C * C; i += 512) {
        int n = i >> 7, k = i & 127;
        uint32_t o = n * ROWB + k * 2;
        *(__half*)(smem + OFF_B1 + o) = g_B1h[i];
        *(__half*)(smem + OFF_B2 + o) = g_B2h[i];
        *(__half*)(smem + OFF_B3 + o) = g_B3h[i];
    }
    float* sBias = (float*)(smem + OFF_BIAS);
    if (tid < C) {
        sBias[tid] = pos_b1[tid];
        sBias[C + tid] = pos_b2[tid];
        sBias[2 * C + tid] = att_b1[tid];
        sBias[3 * C + tid] = att_b2[tid];
    }
    int* sSrc = (int*)(smem + OFF_IDX);
    int* sDst = sSrc + 128;
    __syncthreads();

    const int nbw = wid * 8;
    const int qr = lane >> 2;
    const int qc = 2 * (lane & 3);
    const int lr = lane & 7;
    const int lg = lane >> 3;
    const int cb = nbw + qc;
    const int hf = wid >> 3;
    const int cbl = cb - hf * 64;
    const int bufoff = hf ? OFF_A0 : OFF_S2;

    float acc[8][4];
    uint32_t bf[8][2];

    for (long long tile = blockIdx.x; tile * 128 < E; tile += gridDim.x) {
        long long ebase = tile * 128;
        // current tile indices + next-tile indices (for L2 prefetch)
        int nidx = 0;
        long long nb = ebase + (long long)gridDim.x * 128;
        if (tid < 128) {
            sSrc[tid] = (ebase + tid < E) ? g_src2[ebase + tid] : 0;
            if (nb + tid < E) nidx = g_src2[nb + tid];
        } else if (tid < 256) {
            int j = tid - 128;
            sDst[j] = (ebase + j < E) ? g_dst2[ebase + j] : -1;
            if (nb + j < E) nidx = g_dst2[nb + j];
        }
        __syncthreads();

        // ---- stage G: A0 = relu(P1[dst]-P1[src]+pos_b1) ----
        {
            float4 bp = ((float4*)sBias)[lane];
#pragma unroll 4
            for (int i = 0; i < 8; i++) {
                int e = wid * 8 + i;
                int s = sSrc[e];
                int d = sDst[e]; if (d < 0) d = 0;
                float4 pd = ((const float4*)(g_P1 + (size_t)d * C))[lane];
                float4 ps = ((const float4*)(g_P1 + (size_t)s * C))[lane];
                __half2 h0 = __floats2half2_rn(fmaxf(pd.x - ps.x + bp.x, 0.f),
                                               fmaxf(pd.y - ps.y + bp.y, 0.f));
                __half2 h1 = __floats2half2_rn(fmaxf(pd.z - ps.z + bp.z, 0.f),
                                               fmaxf(pd.w - ps.w + bp.w, 0.f));
                uint2 m;
                m.x = *(unsigned*)&h0;
                m.y = *(unsigned*)&h1;
                *(uint2*)(smem + OFF_A0 + e * ROWB + lane * 8) = m;
            }
        }
        __syncthreads();

#define GEMM(OFFB, OFFA)                                                            \
        {                                                                           \
            _Pragma("unroll")                                                       \
            for (int kt = 0; kt < 8; kt++) {                                        \
                uint32_t a = sbase + (OFFB) + (nbw + lr) * ROWB + kt * 32 +         \
                             (lg & 1) * 16;                                         \
                ldsm_x2(a, bf[kt][0], bf[kt][1]);                                   \
            }                                                                       \
            _Pragma("unroll")                                                       \
            for (int mt = 0; mt < 8; mt++)                                          \
                _Pragma("unroll")                                                   \
                for (int j = 0; j < 4; j++) acc[mt][j] = 0.f;                       \
            _Pragma("unroll 2")                                                     \
            for (int kt = 0; kt < 8; kt++) {                                        \
                _Pragma("unroll")                                                   \
                for (int mt = 0; mt < 8; mt++) {                                    \
                    uint32_t a0, a1, a2, a3;                                        \
                    uint32_t ad = sbase + (OFFA) +                                  \
                                  (mt * 16 + ((lg & 1) << 3) + lr) * ROWB +         \
                                  (kt * 16 + ((lg >> 1) << 3)) * 2;                 \
                    ldsm_x4(ad, a0, a1, a2, a3);                                    \
                    mma_16816(acc[mt], a0, a1, a2, a3, bf[kt][0], bf[kt][1]);       \
                }                                                                   \
            }                                                                       \
        }

        // ===== GEMM1: A0 @ B1^T =====
        GEMM(OFF_B1, OFF_A0)

        // ---- E1: delta = relu(D + pos_b2) -> A1 ----
        {
            float b0 = sBias[C + cb], b1 = sBias[C + cb + 1];
#pragma unroll
            for (int mt = 0; mt < 8; mt++) {
                int r0 = mt * 16 + qr, r1 = r0 + 8;
                __half2 h0 = __floats2half2_rn(fmaxf(acc[mt][0] + b0, 0.f),
                                               fmaxf(acc[mt][1] + b1, 0.f));
                __half2 h1 = __floats2half2_rn(fmaxf(acc[mt][2] + b0, 0.f),
                                               fmaxf(acc[mt][3] + b1, 0.f));
                *(__half2*)(smem + OFF_A1 + r0 * ROWB + cb * 2) = h0;
                *(__half2*)(smem + OFF_A1 + r1 * ROWB + cb * 2) = h1;
            }
        }
        // L2 prefetch of next tile's gather rows (index regs resolved during GEMM1)
        if (nb < E) {
            if (tid < 128) {
                const float* p1 = g_P1 + (size_t)nidx * C;
                const float* kk = g_KK + (size_t)nidx * C;
                const float* vv = g_v + (size_t)nidx * C;
#pragma unroll
                for (int j = 0; j < 4; j++) {
                    PF_L2(p1 + j * 32);
                    PF_L2(kk + j * 32);
                    PF_L2(vv + j * 32);
                }
            } else if (tid < 256) {
                const float* p1 = g_P1 + (size_t)nidx * C;
                const float* qk = g_QK + (size_t)nidx * C;
#pragma unroll
                for (int j = 0; j < 4; j++) {
                    PF_L2(p1 + j * 32);
                    PF_L2(qk + j * 32);
                }
            }
        }
        __syncthreads();

        // ===== GEMM2: A1 @ B2^T =====
        GEMM(OFF_B2, OFF_A1)
        __syncthreads();

        // ---- E2: t2 = relu(QK[dst]-KK[src] + D + att_b1) -> A0 ----
        {
            float b0 = sBias[2 * C + cb], b1 = sBias[2 * C + cb + 1];
#pragma unroll
            for (int mt = 0; mt < 8; mt++) {
                int r0 = mt * 16 + qr, r1 = r0 + 8;
                int d0i = sDst[r0]; if (d0i < 0) d0i = 0;
                int s0i = sSrc[r0];
                int d1i = sDst[r1]; if (d1i < 0) d1i = 0;
                int s1i = sSrc[r1];
                float2 q0 = *(const float2*)(g_QK + (size_t)d0i * C + cb);
                float2 k0 = *(const float2*)(g_KK + (size_t)s0i * C + cb);
                float2 q1 = *(const float2*)(g_QK + (size_t)d1i * C + cb);
                float2 k1 = *(const float2*)(g_KK + (size_t)s1i * C + cb);
                __half2 h0 = __floats2half2_rn(fmaxf(q0.x - k0.x + acc[mt][0] + b0, 0.f),
                                               fmaxf(q0.y - k0.y + acc[mt][1] + b1, 0.f));
                __half2 h1 = __floats2half2_rn(fmaxf(q1.x - k1.x + acc[mt][2] + b0, 0.f),
                                               fmaxf(q1.y - k1.y + acc[mt][3] + b1, 0.f));
                *(__half2*)(smem + OFF_A0 + r0 * ROWB + cb * 2) = h0;
                *(__half2*)(smem + OFF_A0 + r1 * ROWB + cb * 2) = h1;
            }
        }
        __syncthreads();

        // ===== GEMM3: A0(t2) @ B3^T =====
        GEMM(OFF_B3, OFF_A0)
        __syncthreads();   // all GEMM3 A0 reads done before staging reuses A0

        // ---- ez = exp(relu(D + att_b2)) in place ----
        {
            float b0 = sBias[3 * C + cb], b1 = sBias[3 * C + cb + 1];
#pragma unroll
            for (int mt = 0; mt < 8; mt++) {
                acc[mt][0] = __expf(fmaxf(acc[mt][0] + b0, 0.f));
                acc[mt][1] = __expf(fmaxf(acc[mt][1] + b1, 0.f));
                acc[mt][2] = __expf(fmaxf(acc[mt][2] + b0, 0.f));
                acc[mt][3] = __expf(fmaxf(acc[mt][3] + b1, 0.f));
            }
        }

        // ---- stage nm = ez*(v[src]+delta), both halves at once ----
#pragma unroll
        for (int mt = 0; mt < 8; mt++) {
            int r0 = mt * 16 + qr, r1 = r0 + 8;
            int s0i = sSrc[r0], s1i = sSrc[r1];
            float2 v0 = *(const float2*)(g_v + (size_t)s0i * C + cb);
            float2 v1 = *(const float2*)(g_v + (size_t)s1i * C + cb);
            float2 f0 = __half22float2(*(__half2*)(smem + OFF_A1 + r0 * ROWB + cb * 2));
            float2 f1 = __half22float2(*(__half2*)(smem + OFF_A1 + r1 * ROWB + cb * 2));
            float2 n0 = make_float2(acc[mt][0] * (v0.x + f0.x),
                                    acc[mt][1] * (v0.y + f0.y));
            float2 n1 = make_float2(acc[mt][2] * (v1.x + f1.x),
                                    acc[mt][3] * (v1.y + f1.y));
            *(float2*)(smem + bufoff + r0 * ROWB + cbl * 4) = n0;
            *(float2*)(smem + bufoff + r1 * ROWB + cbl * 4) = n1;
        }
        __syncthreads();
        seg_reduce2(smem, sDst, g_num, tid);
        __syncthreads();

        // ---- stage ez, both halves ----
#pragma unroll
        for (int mt = 0; mt < 8; mt++) {
            int r0 = mt * 16 + qr, r1 = r0 + 8;
            *(float2*)(smem + bufoff + r0 * ROWB + cbl * 4) =
                make_float2(acc[mt][0], acc[mt][1]);
            *(float2*)(smem + bufoff + r1 * ROWB + cbl * 4) =
                make_float2(acc[mt][2], acc[mt][3]);
        }
        __syncthreads();
        seg_reduce2(smem, sDst, g_z, tid);
        __syncthreads();
    }
}

// ---------------- out kernel ----------------
#define SZO2 ((C * C + 32 * C + C) * 4)
__global__ void __launch_bounds__(256, 2)
out_kernel(const float* __restrict__ W_out, const float* __restrict__ b_out,
           float* __restrict__ out, int n) {
    extern __shared__ float sm[];
    float* sW = sm;
    float* srow = sm + C * C;
    float* sb = sm + C * C + 32 * C;

    int tid = threadIdx.x;
    for (int i = tid; i < C * C; i += 256) sW[i] = W_out[i];
    if (tid < C) sb[tid] = b_out[tid];
    __syncthreads();

    int cg = tid & 31, ng = tid >> 5;
    int nbase = blockIdx.x * 32 + ng * 4;
#pragma unroll
    for (int i = 0; i < 4; i++) {
        int nn = nbase + i;
        if (nn < n) {
            float4 nm = ((const float4*)&g_num[(size_t)nn * C])[cg];
            float4 zz = ((const float4*)&g_z[(size_t)nn * C])[cg];
            float4 ag;
            ag.x = nm.x / (zz.x + 1e-16f);
            ag.y = nm.y / (zz.y + 1e-16f);
            ag.z = nm.z / (zz.z + 1e-16f);
            ag.w = nm.w / (zz.w + 1e-16f);
            ((float4*)&srow[(ng * 4 + i) * C])[cg] = ag;
        } else {
            ((float4*)&srow[(ng * 4 + i) * C])[cg] = make_float4(0.f, 0.f, 0.f, 0.f);
        }
    }
    __syncwarp();

    float4 acc[4];
#pragma unroll
    for (int i = 0; i < 4; i++) acc[i] = make_float4(0.f, 0.f, 0.f, 0.f);
#pragma unroll 2
    for (int k = 0; k < C; k++) {
        float4 w = ((float4*)sW)[k * 32 + cg];
#pragma unroll
        for (int i = 0; i < 4; i++) {
            float av = srow[(ng * 4 + i) * C + k];
            acc[i].x += av * w.x; acc[i].y += av * w.y;
            acc[i].z += av * w.z; acc[i].w += av * w.w;
        }
    }
    float4 bv = ((float4*)sb)[cg];
#pragma unroll
    for (int i = 0; i < 4; i++) {
        int nn = nbase + i;
        if (nn < n) {
            float4 ov;
            ov.x = fmaxf(acc[i].x + bv.x, 0.f);
            ov.y = fmaxf(acc[i].y + bv.y, 0.f);
            ov.z = fmaxf(acc[i].z + bv.z, 0.f);
            ov.w = fmaxf(acc[i].w + bv.w, 0.f);
            ((float4*)&out[(size_t)nn * C])[cg] = ov;
        }
    }
}

// ---------------- launch ----------------
extern "C" void kernel_launch(void* const* d_in, const int* in_sizes, int n_in,
                              void* d_out, int out_size) {
    const float* x = (const float*)d_in[0];
    const float* pos = (const float*)d_in[1];
    const void* ei = d_in[2];
    const float* W_in = (const float*)d_in[3];
    const float* b_in = (const float*)d_in[4];
    const float* W_lin = (const float*)d_in[5];
    const float* W_src = (const float*)d_in[6];
    const float* W_dst = (const float*)d_in[7];
    const float* pos_w1 = (const float*)d_in[8];
    const float* pos_b1 = (const float*)d_in[9];
    const float* pos_w2 = (const float*)d_in[10];
    const float* pos_b2 = (const float*)d_in[11];
    const float* att_w1 = (const float*)d_in[12];
    const float* att_b1 = (const float*)d_in[13];
    const float* att_w2 = (const float*)d_in[14];
    const float* att_b2 = (const float*)d_in[15];
    const float* W_out = (const float*)d_in[16];
    const float* b_out = (const float*)d_in[17];

    int n = in_sizes[0] / C;
    long long E = in_sizes[2] / 2;
    int eb = (int)((E + 255) / 256);

    cudaFuncSetAttribute(node12_kernel, cudaFuncAttributeMaxDynamicSharedMemorySize, SZ12);
    cudaFuncSetAttribute(edge_mma_kernel, cudaFuncAttributeMaxDynamicSharedMemorySize, SZE);
    cudaFuncSetAttribute(out_kernel, cudaFuncAttributeMaxDynamicSharedMemorySize, SZO2);

    convert_kernel<<<eb, 256>>>(ei, E, n);
    hist_kernel<<<eb, 256>>>(E);
    scan_kernel<<<1, 1024>>>(n);
    scatter_kernel<<<eb, 256>>>(E);

    util_kernel<<<512, 256>>>(W_dst, W_src, att_w1, pos_w2, att_w1, att_w2, n);

    int nb = (n + 31) / 32;
    node12_kernel<<<nb, 256, SZ12>>>(x, pos, W_in, b_in, pos_w1, W_lin, n);

    edge_mma_kernel<<<148, 512, SZE>>>(E, pos_b1, pos_b2, att_b1, att_b2);

    out_kernel<<<nb, 256, SZO2>>>(W_out, b_out, (float*)d_out, n);
}